// round 5
// baseline (speedup 1.0000x reference)
#include <cuda_runtime.h>
#include <cuda_bf16.h>
#include <cstdint>

// Problem constants
#define BATCH 4
#define CIN   256
#define COUT  256
#define HH    64
#define WW    64
#define HW    4096
#define NTAP  9
#define KTOT  2304        // tap-major: k = tap*256 + c
#define NCHUNK 36         // 9 taps * 4 chunks of 64 channels

// ---------------- scratch ----------------
__device__ int4   g_idx[BATCH * NTAP * HW];
__device__ float4 g_wt [BATCH * NTAP * HW];
__device__ __nv_bfloat16 g_bh[COUT * KTOT];   // w_conv  [n][k], k = tap*256 + c
__device__ __nv_bfloat16 g_bl[COUT * KTOT];
__device__ __nv_bfloat16 g_oh[32 * KTOT];     // w_off   [n(27->32)][k]
__device__ __nv_bfloat16 g_ol[32 * KTOT];

// ---------------- helpers ----------------
__device__ __forceinline__ uint32_t smem_u32(const void* p) {
    uint32_t a;
    asm("{ .reg .u64 t; cvta.to.shared.u64 t, %1; cvt.u32.u64 %0, t; }" : "=r"(a) : "l"(p));
    return a;
}
__device__ __forceinline__ void ldm_x4(uint32_t* r, uint32_t addr) {
    asm volatile("ldmatrix.sync.aligned.m8n8.x4.shared.b16 {%0,%1,%2,%3}, [%4];"
                 : "=r"(r[0]), "=r"(r[1]), "=r"(r[2]), "=r"(r[3]) : "r"(addr));
}
__device__ __forceinline__ void mma_bf16(float* c, const uint32_t* a, const uint32_t* b) {
    asm volatile(
        "mma.sync.aligned.m16n8k16.row.col.f32.bf16.bf16.f32 "
        "{%0,%1,%2,%3}, {%4,%5,%6,%7}, {%8,%9}, {%0,%1,%2,%3};"
        : "+f"(c[0]), "+f"(c[1]), "+f"(c[2]), "+f"(c[3])
        : "r"(a[0]), "r"(a[1]), "r"(a[2]), "r"(a[3]), "r"(b[0]), "r"(b[1]));
}
__device__ __forceinline__ void cpasync16(uint32_t dst, const void* src) {
    asm volatile("cp.async.cg.shared.global [%0], [%1], 16;" :: "r"(dst), "l"(src));
}
__device__ __forceinline__ void cpasync8(uint32_t dst, const void* src) {
    asm volatile("cp.async.ca.shared.global [%0], [%1], 8;" :: "r"(dst), "l"(src));
}
#define CP_COMMIT() asm volatile("cp.async.commit_group;")
#define CP_WAIT0()  asm volatile("cp.async.wait_group 0;" ::: "memory")

__device__ __forceinline__ uint32_t pack_bf16x2(float v0, float v1,
                                                uint32_t& lo_out) {
    const __nv_bfloat16 h0 = __float2bfloat16_rn(v0);
    const __nv_bfloat16 h1 = __float2bfloat16_rn(v1);
    const __nv_bfloat16 l0 = __float2bfloat16_rn(v0 - __bfloat162float(h0));
    const __nv_bfloat16 l1 = __float2bfloat16_rn(v1 - __bfloat162float(h1));
    lo_out = (uint32_t)__bfloat16_as_ushort(l0) | ((uint32_t)__bfloat16_as_ushort(l1) << 16);
    return (uint32_t)__bfloat16_as_ushort(h0) | ((uint32_t)__bfloat16_as_ushort(h1) << 16);
}

// ---------------------------------------------------------------------------
// Stage 0: prepack w_conv + w_off -> tap-major bf16 hi/lo
// ---------------------------------------------------------------------------
__global__ __launch_bounds__(256)
void prepack_kernel(const float* __restrict__ w_conv,
                    const float* __restrict__ w_off)
{
    const int i = blockIdx.x * 256 + threadIdx.x;
    if (i < COUT * KTOT) {
        const int n = i / KTOT, k = i % KTOT;
        const int tap = k >> 8, c = k & 255;
        const float w = w_conv[(n * CIN + c) * 9 + tap];
        const __nv_bfloat16 h = __float2bfloat16_rn(w);
        g_bh[i] = h;
        g_bl[i] = __float2bfloat16_rn(w - __bfloat162float(h));
    } else if (i < (COUT + 32) * KTOT) {
        const int j = i - COUT * KTOT;
        const int n = j / KTOT, k = j % KTOT;
        const int tap = k >> 8, c = k & 255;
        const float w = (n < 27) ? w_off[(n * CIN + c) * 9 + tap] : 0.f;
        const __nv_bfloat16 h = __float2bfloat16_rn(w);
        g_oh[j] = h;
        g_ol[j] = __float2bfloat16_rn(w - __bfloat162float(h));
    }
}

// ---------------------------------------------------------------------------
// Stage 1: offset conv on tensor cores (M=128/CTA, N=32, K=2304) + epilogue
// producing bilinear corner indices/weights.
// ---------------------------------------------------------------------------
#define OROWB 144
#define OS_AHI 0
#define OS_ALO (128 * OROWB)                  // 18432
#define OS_BHI (2 * 128 * OROWB)              // 36864
#define OS_BLO (OS_BHI + 32 * OROWB)          // 41472
#define OBUF   (OS_BLO + 32 * OROWB)          // 46080
#define OS_ACC (2 * OBUF)                     // 92160
#define OSMEM_TOTAL (OS_ACC + 128 * 33 * 4)   // 109056

__global__ __launch_bounds__(256, 1)
void offset_mma_kernel(const float* __restrict__ x,
                       const float* __restrict__ b_off)
{
    extern __shared__ char smem[];
    const uint32_t sb = smem_u32(smem);
    const int t    = threadIdx.x;
    const int lane = t & 31;
    const int wid  = t >> 5;
    const int b    = blockIdx.x >> 5;
    const int p0   = (blockIdx.x & 31) * 128;

    const float* xb = x + (size_t)b * CIN * HW;

    const int am = t & 127;
    const int ah = t >> 7;
    const int ph = (p0 + am) >> 6;
    const int pw = (p0 + am) & 63;

    const uint32_t a_row  = (uint32_t)(wid * 16 + (lane & 15));
    const uint32_t a_colb = (uint32_t)((lane >> 4) * 16);
    const uint32_t b_row  = (uint32_t)((lane & 7) + ((lane >> 4) << 3));
    const uint32_t b_colb = (uint32_t)(((lane >> 3) & 1) * 16);

    float acc[4][4];
#pragma unroll
    for (int ni = 0; ni < 4; ni++)
#pragma unroll
        for (int j = 0; j < 4; j++) acc[ni][j] = 0.f;

    auto build_a = [&](int chunk, uint32_t base) {
        const int tap = chunk >> 2;
        const int c0  = (chunk & 3) * 64;
        const int yy = ph - 1 + tap / 3;
        const int xx = pw - 1 + tap % 3;
        const bool ok = (yy >= 0) && (yy < HH) && (xx >= 0) && (xx < WW);
        const int sidx = ok ? (yy * WW + xx) : 0;
        const float* xc = xb + (size_t)(c0 + ah * 32) * HW + sidx;
#pragma unroll
        for (int jj = 0; jj < 16; jj++) {
            const float v0 = ok ? __ldg(xc + (size_t)(2 * jj) * HW) : 0.f;
            const float v1 = ok ? __ldg(xc + (size_t)(2 * jj + 1) * HW) : 0.f;
            uint32_t lo2, hi2 = pack_bf16x2(v0, v1, lo2);
            const uint32_t bo = (uint32_t)(am * OROWB + (ah * 32 + 2 * jj) * 2);
            asm volatile("st.shared.b32 [%0], %1;" :: "r"(base + OS_AHI + bo), "r"(hi2) : "memory");
            asm volatile("st.shared.b32 [%0], %1;" :: "r"(base + OS_ALO + bo), "r"(lo2) : "memory");
        }
    };
    auto build_b = [&](int chunk, uint32_t base) {
        const int tap = chunk >> 2;
        const int c0  = (chunk & 3) * 64;
        const int n = t >> 3, vw = t & 7;
        const size_t gofs = (size_t)n * KTOT + tap * 256 + c0 + vw * 8;
        const uint32_t bo = (uint32_t)(n * OROWB + vw * 16);
        cpasync16(base + OS_BHI + bo, g_oh + gofs);
        cpasync16(base + OS_BLO + bo, g_ol + gofs);
        CP_COMMIT();
    };
    auto compute = [&](uint32_t base) {
        const uint32_t Ah = base + OS_AHI, Al = base + OS_ALO;
        const uint32_t Bh = base + OS_BHI, Bl = base + OS_BLO;
#pragma unroll
        for (int s = 0; s < 4; s++) {
            uint32_t af[4];
            ldm_x4(af, Ah + a_row * OROWB + a_colb + s * 32);
            uint32_t bhf[4][2], blf[4][2];
#pragma unroll
            for (int np = 0; np < 2; np++) {
                uint32_t r[4];
                ldm_x4(r, Bh + (b_row + np * 16) * OROWB + b_colb + s * 32);
                bhf[np * 2][0] = r[0]; bhf[np * 2][1] = r[1];
                bhf[np * 2 + 1][0] = r[2]; bhf[np * 2 + 1][1] = r[3];
                ldm_x4(r, Bl + (b_row + np * 16) * OROWB + b_colb + s * 32);
                blf[np * 2][0] = r[0]; blf[np * 2][1] = r[1];
                blf[np * 2 + 1][0] = r[2]; blf[np * 2 + 1][1] = r[3];
            }
#pragma unroll
            for (int ni = 0; ni < 4; ni++) {
                mma_bf16(acc[ni], af, bhf[ni]);
                mma_bf16(acc[ni], af, blf[ni]);
            }
        }
#pragma unroll
        for (int s = 0; s < 4; s++) {
            uint32_t af[4];
            ldm_x4(af, Al + a_row * OROWB + a_colb + s * 32);
            uint32_t bhf[4][2];
#pragma unroll
            for (int np = 0; np < 2; np++) {
                uint32_t r[4];
                ldm_x4(r, Bh + (b_row + np * 16) * OROWB + b_colb + s * 32);
                bhf[np * 2][0] = r[0]; bhf[np * 2][1] = r[1];
                bhf[np * 2 + 1][0] = r[2]; bhf[np * 2 + 1][1] = r[3];
            }
#pragma unroll
            for (int ni = 0; ni < 4; ni++)
                mma_bf16(acc[ni], af, bhf[ni]);
        }
    };

    build_b(0, sb);
    build_a(0, sb);
    CP_WAIT0();
    __syncthreads();
    for (int chunk = 0; chunk < NCHUNK; chunk++) {
        const uint32_t cur = sb + (uint32_t)(chunk & 1) * OBUF;
        if (chunk + 1 < NCHUNK) {
            const uint32_t nxt = sb + (uint32_t)((chunk + 1) & 1) * OBUF;
            build_b(chunk + 1, nxt);
            build_a(chunk + 1, nxt);
        }
        compute(cur);
        CP_WAIT0();
        __syncthreads();
    }

    float* sacc = reinterpret_cast<float*>(smem + OS_ACC);
    const int mb = wid * 16 + (lane >> 2);
    const int nb = (lane & 3) * 2;
#pragma unroll
    for (int ni = 0; ni < 4; ni++) {
        const int n = nb + ni * 8;
        sacc[mb * 33 + n]           = acc[ni][0];
        sacc[mb * 33 + n + 1]       = acc[ni][1];
        sacc[(mb + 8) * 33 + n]     = acc[ni][2];
        sacc[(mb + 8) * 33 + n + 1] = acc[ni][3];
    }
    __syncthreads();

    if (t < 128) {
        const int p = p0 + t;
        const int h = p >> 6, w = p & 63;
        const float* row = sacc + t * 33;
#pragma unroll
        for (int k = 0; k < NTAP; k++) {
            const float dy = row[2 * k]     + __ldg(b_off + 2 * k);
            const float dx = row[2 * k + 1] + __ldg(b_off + 2 * k + 1);
            const float mz = row[18 + k]    + __ldg(b_off + 18 + k);
            const float m  = 1.f / (1.f + expf(-mz));

            const float py = dy + (float)(h - 1 + k / 3);
            const float px = dx + (float)(w - 1 + k % 3);
            const float y0 = floorf(py);
            const float x0 = floorf(px);
            const float wy = py - y0;
            const float wx = px - x0;

            const float cy[2]  = { y0, y0 + 1.f };
            const float cx[2]  = { x0, x0 + 1.f };
            const float wyv[2] = { 1.f - wy, wy };
            const float wxv[2] = { 1.f - wx, wx };

            int   idxv[4];
            float wtv[4];
#pragma unroll
            for (int jy = 0; jy < 2; jy++) {
#pragma unroll
                for (int jx = 0; jx < 2; jx++) {
                    const float yc = cy[jy], xc = cx[jx];
                    const bool valid = (yc >= 0.f) && (yc <= (float)(HH - 1)) &&
                                       (xc >= 0.f) && (xc <= (float)(WW - 1));
                    const int yi = (int)fminf(fmaxf(yc, 0.f), (float)(HH - 1));
                    const int xi = (int)fminf(fmaxf(xc, 0.f), (float)(WW - 1));
                    const int j = jy * 2 + jx;
                    idxv[j] = yi * WW + xi;
                    wtv[j]  = valid ? (wyv[jy] * wxv[jx] * m) : 0.f;
                }
            }
            const int o = (b * NTAP + k) * HW + p;
            g_idx[o] = make_int4(idxv[0], idxv[1], idxv[2], idxv[3]);
            g_wt[o]  = make_float4(wtv[0], wtv[1], wtv[2], wtv[3]);
        }
    }
}

// ---------------------------------------------------------------------------
// Stage 2: implicit GEMM via mma.sync bf16 (hi/lo x3-term fp32 emulation).
// 128 pixels x 256 couts per CTA, 512 threads (16 warps, 2m x 8n).
// Distance-2 gather pipeline; per-tap meta staged in smem via cp.async.
// ---------------------------------------------------------------------------
#define ROWB   144
#define SM_AHI 0
#define SM_ALO (128 * ROWB)
#define SM_BHI (2 * 128 * ROWB)
#define SM_BLO (SM_BHI + 256 * ROWB)
#define BUF_BYTES (SM_BLO + 256 * ROWB)       // 110592
#define META_OFF  (2 * BUF_BYTES)             // 221184; 2 slots x 4KB
#define SMEM_TOTAL (META_OFF + 8192)          // 229376

__global__ __launch_bounds__(512, 1)
void mma_kernel(const float* __restrict__ x, float* __restrict__ out)
{
    extern __shared__ char smem[];
    const uint32_t sb = smem_u32(smem);
    const int t    = threadIdx.x;
    const int lane = t & 31;
    const int wid  = t >> 5;
    const int b    = blockIdx.x >> 5;
    const int p0   = (blockIdx.x & 31) * 128;

    const float* xb = x + (size_t)b * CIN * HW;

    const int am = t & 127;   // pixel
    const int aq = t >> 7;    // channel quarter (16 ch)

    const int mw = wid & 1;
    const int nw = wid >> 1;

    float acc[4][4][4];
#pragma unroll
    for (int mi = 0; mi < 4; mi++)
#pragma unroll
        for (int ni = 0; ni < 4; ni++)
#pragma unroll
            for (int j = 0; j < 4; j++) acc[mi][ni][j] = 0.f;

    const uint32_t a_row  = (uint32_t)(mw * 64 + (lane & 15));
    const uint32_t a_colb = (uint32_t)((lane >> 4) * 16);
    const uint32_t b_row  = (uint32_t)(nw * 32 + (lane & 7) + ((lane >> 4) << 3));
    const uint32_t b_colb = (uint32_t)(((lane >> 3) & 1) * 16);

    // ---- next-chunk build state ----
    int4   idn;
    float4 wtn;
    const float* xcn = xb;
    uint32_t nbase = sb;

    // meta staging: slot = tap&1, 4KB each (idx 2KB + wt 2KB)
    auto meta_async = [&](int tap) {
        const uint32_t slot = sb + META_OFF + (uint32_t)(tap & 1) * 4096;
        const int base_off = (b * NTAP + tap) * HW + p0;
        if (t < 256) {
            cpasync8(slot + (uint32_t)t * 8,
                     reinterpret_cast<const char*>(g_idx + base_off) + t * 8);
        } else {
            const int u = t - 256;
            cpasync8(slot + 2048 + (uint32_t)u * 8,
                     reinterpret_cast<const char*>(g_wt + base_off) + u * 8);
        }
    };
    auto meta_read = [&](int chunk, uint32_t base) {
        const int tap = chunk >> 2;
        const int c0  = (chunk & 3) * 64;
        const uint32_t slot = sb + META_OFF + (uint32_t)(tap & 1) * 4096;
        asm volatile("ld.shared.v4.b32 {%0,%1,%2,%3}, [%4];"
                     : "=r"(*(uint32_t*)&idn.x), "=r"(*(uint32_t*)&idn.y),
                       "=r"(*(uint32_t*)&idn.z), "=r"(*(uint32_t*)&idn.w)
                     : "r"(slot + (uint32_t)am * 16));
        asm volatile("ld.shared.v4.b32 {%0,%1,%2,%3}, [%4];"
                     : "=f"(wtn.x), "=f"(wtn.y), "=f"(wtn.z), "=f"(wtn.w)
                     : "r"(slot + 2048 + (uint32_t)am * 16));
        xcn = xb + (size_t)(c0 + aq * 16) * HW;
        nbase = base;
    };
    auto a_load8 = [&](int g, float* v) {
        const float* xp0 = xcn + (size_t)(2 * g) * HW;
        const float* xp1 = xp0 + HW;
        v[0] = __ldg(xp0 + idn.x); v[1] = __ldg(xp0 + idn.y);
        v[2] = __ldg(xp0 + idn.z); v[3] = __ldg(xp0 + idn.w);
        v[4] = __ldg(xp1 + idn.x); v[5] = __ldg(xp1 + idn.y);
        v[6] = __ldg(xp1 + idn.z); v[7] = __ldg(xp1 + idn.w);
    };
    auto a_finish = [&](int g, const float* v) {
        const float v0 = wtn.x * v[0] + wtn.y * v[1] + wtn.z * v[2] + wtn.w * v[3];
        const float v1 = wtn.x * v[4] + wtn.y * v[5] + wtn.z * v[6] + wtn.w * v[7];
        uint32_t lo2, hi2 = pack_bf16x2(v0, v1, lo2);
        const uint32_t bo = (uint32_t)(am * ROWB + (aq * 16 + 2 * g) * 2);
        asm volatile("st.shared.b32 [%0], %1;" :: "r"(nbase + SM_AHI + bo), "r"(hi2) : "memory");
        asm volatile("st.shared.b32 [%0], %1;" :: "r"(nbase + SM_ALO + bo), "r"(lo2) : "memory");
    };
    auto b_async = [&](int chunk, uint32_t base) {
        const int tap = chunk >> 2;
        const int c0  = (chunk & 3) * 64;
#pragma unroll
        for (int q2 = 0; q2 < 4; q2++) {
            const int v2 = t + 512 * q2;
            const int n = v2 >> 3, vw = v2 & 7;
            const size_t gofs = (size_t)n * KTOT + tap * 256 + c0 + vw * 8;
            const uint32_t bo = (uint32_t)(n * ROWB + vw * 16);
            cpasync16(base + SM_BHI + bo, g_bh + gofs);
            cpasync16(base + SM_BLO + bo, g_bl + gofs);
        }
    };

    auto pass1_step = [&](uint32_t base, int s) {
        const uint32_t Ah = base + SM_AHI;
        const uint32_t Bh = base + SM_BHI, Bl = base + SM_BLO;
        uint32_t bhf[4][2], blf[4][2];
#pragma unroll
        for (int np = 0; np < 2; np++) {
            uint32_t r[4];
            ldm_x4(r, Bh + (b_row + np * 16) * ROWB + b_colb + s * 32);
            bhf[np * 2][0] = r[0]; bhf[np * 2][1] = r[1];
            bhf[np * 2 + 1][0] = r[2]; bhf[np * 2 + 1][1] = r[3];
            ldm_x4(r, Bl + (b_row + np * 16) * ROWB + b_colb + s * 32);
            blf[np * 2][0] = r[0]; blf[np * 2][1] = r[1];
            blf[np * 2 + 1][0] = r[2]; blf[np * 2 + 1][1] = r[3];
        }
#pragma unroll
        for (int mi = 0; mi < 4; mi++) {
            uint32_t af[4];
            ldm_x4(af, Ah + (a_row + mi * 16) * ROWB + a_colb + s * 32);
#pragma unroll
            for (int ni = 0; ni < 4; ni++) {
                mma_bf16(acc[mi][ni], af, bhf[ni]);
                mma_bf16(acc[mi][ni], af, blf[ni]);
            }
        }
    };
    auto pass2_step = [&](uint32_t base, int s) {
        const uint32_t Al = base + SM_ALO;
        const uint32_t Bh = base + SM_BHI;
        uint32_t bhf[4][2];
#pragma unroll
        for (int np = 0; np < 2; np++) {
            uint32_t r[4];
            ldm_x4(r, Bh + (b_row + np * 16) * ROWB + b_colb + s * 32);
            bhf[np * 2][0] = r[0]; bhf[np * 2][1] = r[1];
            bhf[np * 2 + 1][0] = r[2]; bhf[np * 2 + 1][1] = r[3];
        }
#pragma unroll
        for (int mi = 0; mi < 4; mi++) {
            uint32_t af[4];
            ldm_x4(af, Al + (a_row + mi * 16) * ROWB + a_colb + s * 32);
#pragma unroll
            for (int ni = 0; ni < 4; ni++)
                mma_bf16(acc[mi][ni], af, bhf[ni]);
        }
    };

    // ---- prologue: stage meta(tap0) + B(0), then build chunk 0 ----
    meta_async(0);
    CP_COMMIT();
    b_async(0, sb);
    CP_COMMIT();
    CP_WAIT0();
    __syncthreads();
    meta_read(0, sb);
    {
        float v[8];
#pragma unroll
        for (int g = 0; g < 8; g++) { a_load8(g, v); a_finish(g, v); }
    }
    __syncthreads();

    // ---- pipelined K loop ----
    for (int chunk = 0; chunk < NCHUNK; chunk++) {
        const uint32_t cur = sb + (uint32_t)(chunk & 1) * BUF_BYTES;
        const bool hn = (chunk + 1 < NCHUNK);
        float v0[8], v1[8];
        if (hn) {
            const uint32_t nxt = sb + (uint32_t)((chunk + 1) & 1) * BUF_BYTES;
            b_async(chunk + 1, nxt);
            if (chunk + 2 < NCHUNK && ((chunk + 2) & 3) == 0)
                meta_async((chunk + 2) >> 2);
            CP_COMMIT();
            meta_read(chunk + 1, nxt);
            a_load8(0, v0);
            a_load8(1, v1);
        }
        pass1_step(cur, 0);
        pass1_step(cur, 1);
        if (hn) { a_finish(0, v0); a_load8(2, v0); }
        pass1_step(cur, 2);
        if (hn) { a_finish(1, v1); a_load8(3, v1); }
        pass1_step(cur, 3);
        if (hn) { a_finish(2, v0); a_load8(4, v0); }
        pass2_step(cur, 0);
        if (hn) { a_finish(3, v1); a_load8(5, v1); }
        pass2_step(cur, 1);
        if (hn) { a_finish(4, v0); a_load8(6, v0); }
        pass2_step(cur, 2);
        if (hn) { a_finish(5, v1); a_load8(7, v1); }
        pass2_step(cur, 3);
        if (hn) { a_finish(6, v0); a_finish(7, v1); }
        if (hn) CP_WAIT0();
        __syncthreads();
    }

    // ---- epilogue ----
    float* ob = out + (size_t)b * COUT * HW + p0;
    const int mbase = mw * 64 + (lane >> 2);
    const int nbase2 = nw * 32 + (lane & 3) * 2;
#pragma unroll
    for (int mi = 0; mi < 4; mi++) {
#pragma unroll
        for (int ni = 0; ni < 4; ni++) {
            const int m = mbase + mi * 16;
            const int n = nbase2 + ni * 8;
            ob[(size_t)n * HW + m]           = acc[mi][ni][0];
            ob[(size_t)(n + 1) * HW + m]     = acc[mi][ni][1];
            ob[(size_t)n * HW + m + 8]       = acc[mi][ni][2];
            ob[(size_t)(n + 1) * HW + m + 8] = acc[mi][ni][3];
        }
    }
}

// ---------------------------------------------------------------------------
extern "C" void kernel_launch(void* const* d_in, const int* in_sizes, int n_in,
                              void* d_out, int out_size)
{
    (void)in_sizes; (void)n_in; (void)out_size;
    const float* x      = (const float*)d_in[0];
    const float* w_off  = (const float*)d_in[1];
    const float* b_off  = (const float*)d_in[2];
    const float* w_conv = (const float*)d_in[3];
    float* out = (float*)d_out;

    cudaFuncSetAttribute(mma_kernel,
                         cudaFuncAttributeMaxDynamicSharedMemorySize, SMEM_TOTAL);
    cudaFuncSetAttribute(offset_mma_kernel,
                         cudaFuncAttributeMaxDynamicSharedMemorySize, OSMEM_TOTAL);

    prepack_kernel<<<((COUT + 32) * KTOT + 255) / 256, 256>>>(w_conv, w_off);
    offset_mma_kernel<<<128, 256, OSMEM_TOTAL>>>(x, b_off);
    mma_kernel<<<128, 512, SMEM_TOTAL>>>(x, out);
}

// round 6
// speedup vs baseline: 1.2510x; 1.2510x over previous
#include <cuda_runtime.h>
#include <cuda_bf16.h>
#include <cuda_fp16.h>
#include <cstdint>

// Problem constants
#define BATCH 4
#define CIN   256
#define COUT  256
#define HH    64
#define WW    64
#define HW    4096
#define NTAP  9
#define KTOT  2304        // tap-major: k = tap*256 + c
#define NCHUNK 36         // 9 taps * 4 chunks of 64 channels

// ---------------- scratch ----------------
__device__ int4   g_idx[BATCH * NTAP * HW];
__device__ float4 g_wt [BATCH * NTAP * HW];
__device__ __half        g_bf[COUT * KTOT];   // w_conv fp16 [n][k], k = tap*256 + c
__device__ __nv_bfloat16 g_oh[32 * KTOT];     // w_off bf16 hi [n(27->32)][k]
__device__ __nv_bfloat16 g_ol[32 * KTOT];     // w_off bf16 lo

// ---------------- helpers ----------------
__device__ __forceinline__ uint32_t smem_u32(const void* p) {
    uint32_t a;
    asm("{ .reg .u64 t; cvta.to.shared.u64 t, %1; cvt.u32.u64 %0, t; }" : "=r"(a) : "l"(p));
    return a;
}
__device__ __forceinline__ void ldm_x4(uint32_t* r, uint32_t addr) {
    asm volatile("ldmatrix.sync.aligned.m8n8.x4.shared.b16 {%0,%1,%2,%3}, [%4];"
                 : "=r"(r[0]), "=r"(r[1]), "=r"(r[2]), "=r"(r[3]) : "r"(addr));
}
__device__ __forceinline__ void mma_bf16(float* c, const uint32_t* a, const uint32_t* b) {
    asm volatile(
        "mma.sync.aligned.m16n8k16.row.col.f32.bf16.bf16.f32 "
        "{%0,%1,%2,%3}, {%4,%5,%6,%7}, {%8,%9}, {%0,%1,%2,%3};"
        : "+f"(c[0]), "+f"(c[1]), "+f"(c[2]), "+f"(c[3])
        : "r"(a[0]), "r"(a[1]), "r"(a[2]), "r"(a[3]), "r"(b[0]), "r"(b[1]));
}
__device__ __forceinline__ void mma_fp16(float* c, const uint32_t* a, const uint32_t* b) {
    asm volatile(
        "mma.sync.aligned.m16n8k16.row.col.f32.f16.f16.f32 "
        "{%0,%1,%2,%3}, {%4,%5,%6,%7}, {%8,%9}, {%0,%1,%2,%3};"
        : "+f"(c[0]), "+f"(c[1]), "+f"(c[2]), "+f"(c[3])
        : "r"(a[0]), "r"(a[1]), "r"(a[2]), "r"(a[3]), "r"(b[0]), "r"(b[1]));
}
__device__ __forceinline__ void cpasync16(uint32_t dst, const void* src) {
    asm volatile("cp.async.cg.shared.global [%0], [%1], 16;" :: "r"(dst), "l"(src));
}
#define CP_COMMIT() asm volatile("cp.async.commit_group;")
#define CP_WAIT0()  asm volatile("cp.async.wait_group 0;" ::: "memory")

__device__ __forceinline__ uint32_t pack_bf16x2(float v0, float v1,
                                                uint32_t& lo_out) {
    const __nv_bfloat16 h0 = __float2bfloat16_rn(v0);
    const __nv_bfloat16 h1 = __float2bfloat16_rn(v1);
    const __nv_bfloat16 l0 = __float2bfloat16_rn(v0 - __bfloat162float(h0));
    const __nv_bfloat16 l1 = __float2bfloat16_rn(v1 - __bfloat162float(h1));
    lo_out = (uint32_t)__bfloat16_as_ushort(l0) | ((uint32_t)__bfloat16_as_ushort(l1) << 16);
    return (uint32_t)__bfloat16_as_ushort(h0) | ((uint32_t)__bfloat16_as_ushort(h1) << 16);
}
__device__ __forceinline__ uint32_t pack_f16x2(float v0, float v1,
                                               uint32_t& lo_out) {
    const __half h0 = __float2half_rn(v0);
    const __half h1 = __float2half_rn(v1);
    const __half l0 = __float2half_rn(v0 - __half2float(h0));
    const __half l1 = __float2half_rn(v1 - __half2float(h1));
    lo_out = (uint32_t)__half_as_ushort(l0) | ((uint32_t)__half_as_ushort(l1) << 16);
    return (uint32_t)__half_as_ushort(h0) | ((uint32_t)__half_as_ushort(h1) << 16);
}

// ---------------------------------------------------------------------------
// Stage 0: prepack w_conv (fp16) + w_off (bf16 hi/lo), tap-major
// ---------------------------------------------------------------------------
__global__ __launch_bounds__(256)
void prepack_kernel(const float* __restrict__ w_conv,
                    const float* __restrict__ w_off)
{
    const int i = blockIdx.x * 256 + threadIdx.x;
    if (i < COUT * KTOT) {
        const int n = i / KTOT, k = i % KTOT;
        const int tap = k >> 8, c = k & 255;
        g_bf[i] = __float2half_rn(w_conv[(n * CIN + c) * 9 + tap]);
    } else if (i < (COUT + 32) * KTOT) {
        const int j = i - COUT * KTOT;
        const int n = j / KTOT, k = j % KTOT;
        const int tap = k >> 8, c = k & 255;
        const float w = (n < 27) ? w_off[(n * CIN + c) * 9 + tap] : 0.f;
        const __nv_bfloat16 h = __float2bfloat16_rn(w);
        g_oh[j] = h;
        g_ol[j] = __float2bfloat16_rn(w - __bfloat162float(h));
    }
}

// ---------------------------------------------------------------------------
// Stage 1: offset conv on tensor cores (M=128/CTA, N=32, K=2304) + epilogue
// producing bilinear corner indices/weights.  (3-term bf16, unchanged)
// ---------------------------------------------------------------------------
#define OROWB 144
#define OS_AHI 0
#define OS_ALO (128 * OROWB)
#define OS_BHI (2 * 128 * OROWB)
#define OS_BLO (OS_BHI + 32 * OROWB)
#define OBUF   (OS_BLO + 32 * OROWB)          // 46080
#define OS_ACC (2 * OBUF)                     // 92160
#define OSMEM_TOTAL (OS_ACC + 128 * 33 * 4)   // 109056

__global__ __launch_bounds__(256, 1)
void offset_mma_kernel(const float* __restrict__ x,
                       const float* __restrict__ b_off)
{
    extern __shared__ char smem[];
    const uint32_t sb = smem_u32(smem);
    const int t    = threadIdx.x;
    const int lane = t & 31;
    const int wid  = t >> 5;
    const int b    = blockIdx.x >> 5;
    const int p0   = (blockIdx.x & 31) * 128;

    const float* xb = x + (size_t)b * CIN * HW;

    const int am = t & 127;
    const int ah = t >> 7;
    const int ph = (p0 + am) >> 6;
    const int pw = (p0 + am) & 63;

    const uint32_t a_row  = (uint32_t)(wid * 16 + (lane & 15));
    const uint32_t a_colb = (uint32_t)((lane >> 4) * 16);
    const uint32_t b_row  = (uint32_t)((lane & 7) + ((lane >> 4) << 3));
    const uint32_t b_colb = (uint32_t)(((lane >> 3) & 1) * 16);

    float acc[4][4];
#pragma unroll
    for (int ni = 0; ni < 4; ni++)
#pragma unroll
        for (int j = 0; j < 4; j++) acc[ni][j] = 0.f;

    auto build_a = [&](int chunk, uint32_t base) {
        const int tap = chunk >> 2;
        const int c0  = (chunk & 3) * 64;
        const int yy = ph - 1 + tap / 3;
        const int xx = pw - 1 + tap % 3;
        const bool ok = (yy >= 0) && (yy < HH) && (xx >= 0) && (xx < WW);
        const int sidx = ok ? (yy * WW + xx) : 0;
        const float* xc = xb + (size_t)(c0 + ah * 32) * HW + sidx;
#pragma unroll
        for (int jj = 0; jj < 16; jj++) {
            const float v0 = ok ? __ldg(xc + (size_t)(2 * jj) * HW) : 0.f;
            const float v1 = ok ? __ldg(xc + (size_t)(2 * jj + 1) * HW) : 0.f;
            uint32_t lo2, hi2 = pack_bf16x2(v0, v1, lo2);
            const uint32_t bo = (uint32_t)(am * OROWB + (ah * 32 + 2 * jj) * 2);
            asm volatile("st.shared.b32 [%0], %1;" :: "r"(base + OS_AHI + bo), "r"(hi2) : "memory");
            asm volatile("st.shared.b32 [%0], %1;" :: "r"(base + OS_ALO + bo), "r"(lo2) : "memory");
        }
    };
    auto build_b = [&](int chunk, uint32_t base) {
        const int tap = chunk >> 2;
        const int c0  = (chunk & 3) * 64;
        const int n = t >> 3, vw = t & 7;
        const size_t gofs = (size_t)n * KTOT + tap * 256 + c0 + vw * 8;
        const uint32_t bo = (uint32_t)(n * OROWB + vw * 16);
        cpasync16(base + OS_BHI + bo, g_oh + gofs);
        cpasync16(base + OS_BLO + bo, g_ol + gofs);
        CP_COMMIT();
    };
    auto compute = [&](uint32_t base) {
        const uint32_t Ah = base + OS_AHI, Al = base + OS_ALO;
        const uint32_t Bh = base + OS_BHI, Bl = base + OS_BLO;
#pragma unroll
        for (int s = 0; s < 4; s++) {
            uint32_t af[4];
            ldm_x4(af, Ah + a_row * OROWB + a_colb + s * 32);
            uint32_t bhf[4][2], blf[4][2];
#pragma unroll
            for (int np = 0; np < 2; np++) {
                uint32_t r[4];
                ldm_x4(r, Bh + (b_row + np * 16) * OROWB + b_colb + s * 32);
                bhf[np * 2][0] = r[0]; bhf[np * 2][1] = r[1];
                bhf[np * 2 + 1][0] = r[2]; bhf[np * 2 + 1][1] = r[3];
                ldm_x4(r, Bl + (b_row + np * 16) * OROWB + b_colb + s * 32);
                blf[np * 2][0] = r[0]; blf[np * 2][1] = r[1];
                blf[np * 2 + 1][0] = r[2]; blf[np * 2 + 1][1] = r[3];
            }
#pragma unroll
            for (int ni = 0; ni < 4; ni++) {
                mma_bf16(acc[ni], af, bhf[ni]);
                mma_bf16(acc[ni], af, blf[ni]);
            }
        }
#pragma unroll
        for (int s = 0; s < 4; s++) {
            uint32_t af[4];
            ldm_x4(af, Al + a_row * OROWB + a_colb + s * 32);
            uint32_t bhf[4][2];
#pragma unroll
            for (int np = 0; np < 2; np++) {
                uint32_t r[4];
                ldm_x4(r, Bh + (b_row + np * 16) * OROWB + b_colb + s * 32);
                bhf[np * 2][0] = r[0]; bhf[np * 2][1] = r[1];
                bhf[np * 2 + 1][0] = r[2]; bhf[np * 2 + 1][1] = r[3];
            }
#pragma unroll
            for (int ni = 0; ni < 4; ni++)
                mma_bf16(acc[ni], af, bhf[ni]);
        }
    };

    build_b(0, sb);
    build_a(0, sb);
    CP_WAIT0();
    __syncthreads();
    for (int chunk = 0; chunk < NCHUNK; chunk++) {
        const uint32_t cur = sb + (uint32_t)(chunk & 1) * OBUF;
        if (chunk + 1 < NCHUNK) {
            const uint32_t nxt = sb + (uint32_t)((chunk + 1) & 1) * OBUF;
            build_b(chunk + 1, nxt);
            build_a(chunk + 1, nxt);
        }
        compute(cur);
        CP_WAIT0();
        __syncthreads();
    }

    float* sacc = reinterpret_cast<float*>(smem + OS_ACC);
    const int mb = wid * 16 + (lane >> 2);
    const int nb = (lane & 3) * 2;
#pragma unroll
    for (int ni = 0; ni < 4; ni++) {
        const int n = nb + ni * 8;
        sacc[mb * 33 + n]           = acc[ni][0];
        sacc[mb * 33 + n + 1]       = acc[ni][1];
        sacc[(mb + 8) * 33 + n]     = acc[ni][2];
        sacc[(mb + 8) * 33 + n + 1] = acc[ni][3];
    }
    __syncthreads();

    if (t < 128) {
        const int p = p0 + t;
        const int h = p >> 6, w = p & 63;
        const float* row = sacc + t * 33;
#pragma unroll
        for (int k = 0; k < NTAP; k++) {
            const float dy = row[2 * k]     + __ldg(b_off + 2 * k);
            const float dx = row[2 * k + 1] + __ldg(b_off + 2 * k + 1);
            const float mz = row[18 + k]    + __ldg(b_off + 18 + k);
            const float m  = 1.f / (1.f + expf(-mz));

            const float py = dy + (float)(h - 1 + k / 3);
            const float px = dx + (float)(w - 1 + k % 3);
            const float y0 = floorf(py);
            const float x0 = floorf(px);
            const float wy = py - y0;
            const float wx = px - x0;

            const float cy[2]  = { y0, y0 + 1.f };
            const float cx[2]  = { x0, x0 + 1.f };
            const float wyv[2] = { 1.f - wy, wy };
            const float wxv[2] = { 1.f - wx, wx };

            int   idxv[4];
            float wtv[4];
#pragma unroll
            for (int jy = 0; jy < 2; jy++) {
#pragma unroll
                for (int jx = 0; jx < 2; jx++) {
                    const float yc = cy[jy], xc = cx[jx];
                    const bool valid = (yc >= 0.f) && (yc <= (float)(HH - 1)) &&
                                       (xc >= 0.f) && (xc <= (float)(WW - 1));
                    const int yi = (int)fminf(fmaxf(yc, 0.f), (float)(HH - 1));
                    const int xi = (int)fminf(fmaxf(xc, 0.f), (float)(WW - 1));
                    const int j = jy * 2 + jx;
                    idxv[j] = yi * WW + xi;
                    wtv[j]  = valid ? (wyv[jy] * wxv[jx] * m) : 0.f;
                }
            }
            const int o = (b * NTAP + k) * HW + p;
            g_idx[o] = make_int4(idxv[0], idxv[1], idxv[2], idxv[3]);
            g_wt[o]  = make_float4(wtv[0], wtv[1], wtv[2], wtv[3]);
        }
    }
}

// ---------------------------------------------------------------------------
// Stage 2: implicit GEMM via mma.sync fp16, 2-term emulation:
//   A split hi/lo fp16, B single fp16 -> Ah*B + Al*B  (2 MMAs per k-step)
// 128 pixels x 256 couts per CTA, 512 threads (16 warps, 2m x 8n).
// A-gather for NEXT chunk interleaved with HMMA of CURRENT (R4 skeleton).
// ---------------------------------------------------------------------------
#define ROWB   144
#define SM_AHI 0
#define SM_ALO (128 * ROWB)                   // 18432
#define SM_B   (2 * 128 * ROWB)               // 36864
#define BUF_BYTES (SM_B + 256 * ROWB)         // 73728
#define SMEM_TOTAL (2 * BUF_BYTES)            // 147456

__global__ __launch_bounds__(512, 1)
void mma_kernel(const float* __restrict__ x, float* __restrict__ out)
{
    extern __shared__ char smem[];
    const uint32_t sb = smem_u32(smem);
    const int t    = threadIdx.x;
    const int lane = t & 31;
    const int wid  = t >> 5;
    const int b    = blockIdx.x >> 5;
    const int p0   = (blockIdx.x & 31) * 128;

    const float* xb = x + (size_t)b * CIN * HW;

    const int am = t & 127;   // pixel
    const int aq = t >> 7;    // channel quarter (16 ch)

    const int mw = wid & 1;
    const int nw = wid >> 1;

    float acc[4][4][4];
#pragma unroll
    for (int mi = 0; mi < 4; mi++)
#pragma unroll
        for (int ni = 0; ni < 4; ni++)
#pragma unroll
            for (int j = 0; j < 4; j++) acc[mi][ni][j] = 0.f;

    const uint32_t a_row  = (uint32_t)(mw * 64 + (lane & 15));
    const uint32_t a_colb = (uint32_t)((lane >> 4) * 16);
    const uint32_t b_row  = (uint32_t)(nw * 32 + (lane & 7) + ((lane >> 4) << 3));
    const uint32_t b_colb = (uint32_t)(((lane >> 3) & 1) * 16);

    // ---- next-chunk build state ----
    int4   idn;
    float4 wtn;
    const float* xcn = xb;
    uint32_t nbase = sb;

    auto set_meta = [&](int chunk, uint32_t base) {
        const int tap = chunk >> 2;
        const int c0  = (chunk & 3) * 64;
        const int off = (b * NTAP + tap) * HW + p0 + am;
        idn = g_idx[off];
        wtn = g_wt[off];
        xcn = xb + (size_t)(c0 + aq * 16) * HW;
        nbase = base;
    };
    auto a_load8 = [&](int g, float* v) {
        const float* xp0 = xcn + (size_t)(2 * g) * HW;
        const float* xp1 = xp0 + HW;
        v[0] = __ldg(xp0 + idn.x); v[1] = __ldg(xp0 + idn.y);
        v[2] = __ldg(xp0 + idn.z); v[3] = __ldg(xp0 + idn.w);
        v[4] = __ldg(xp1 + idn.x); v[5] = __ldg(xp1 + idn.y);
        v[6] = __ldg(xp1 + idn.z); v[7] = __ldg(xp1 + idn.w);
    };
    auto a_finish = [&](int g, const float* v) {
        const float v0 = wtn.x * v[0] + wtn.y * v[1] + wtn.z * v[2] + wtn.w * v[3];
        const float v1 = wtn.x * v[4] + wtn.y * v[5] + wtn.z * v[6] + wtn.w * v[7];
        uint32_t lo2, hi2 = pack_f16x2(v0, v1, lo2);
        const uint32_t bo = (uint32_t)(am * ROWB + (aq * 16 + 2 * g) * 2);
        asm volatile("st.shared.b32 [%0], %1;" :: "r"(nbase + SM_AHI + bo), "r"(hi2) : "memory");
        asm volatile("st.shared.b32 [%0], %1;" :: "r"(nbase + SM_ALO + bo), "r"(lo2) : "memory");
    };
    auto b_async = [&](int chunk, uint32_t base) {
        const int tap = chunk >> 2;
        const int c0  = (chunk & 3) * 64;
#pragma unroll
        for (int q2 = 0; q2 < 4; q2++) {
            const int v2 = t + 512 * q2;      // 0..2047 over (n, 16B-vec)
            const int n = v2 >> 3, vw = v2 & 7;
            const size_t gofs = (size_t)n * KTOT + tap * 256 + c0 + vw * 8;
            const uint32_t bo = (uint32_t)(n * ROWB + vw * 16);
            cpasync16(base + SM_B + bo, g_bf + gofs);
        }
        CP_COMMIT();
    };

    auto pass_step = [&](uint32_t base, uint32_t a_off, int s) {
        const uint32_t A = base + a_off;
        const uint32_t B = base + SM_B;
        uint32_t bf[4][2];
#pragma unroll
        for (int np = 0; np < 2; np++) {
            uint32_t r[4];
            ldm_x4(r, B + (b_row + np * 16) * ROWB + b_colb + s * 32);
            bf[np * 2][0] = r[0]; bf[np * 2][1] = r[1];
            bf[np * 2 + 1][0] = r[2]; bf[np * 2 + 1][1] = r[3];
        }
#pragma unroll
        for (int mi = 0; mi < 4; mi++) {
            uint32_t af[4];
            ldm_x4(af, A + (a_row + mi * 16) * ROWB + a_colb + s * 32);
#pragma unroll
            for (int ni = 0; ni < 4; ni++)
                mma_fp16(acc[mi][ni], af, bf[ni]);
        }
    };

    // ---- prologue: build chunk 0 ----
    b_async(0, sb);
    set_meta(0, sb);
    {
        float v[8];
#pragma unroll
        for (int g = 0; g < 8; g++) { a_load8(g, v); a_finish(g, v); }
    }
    CP_WAIT0();
    __syncthreads();

    // ---- pipelined K loop ----
    for (int chunk = 0; chunk < NCHUNK; chunk++) {
        const uint32_t cur = sb + (uint32_t)(chunk & 1) * BUF_BYTES;
        const bool hn = (chunk + 1 < NCHUNK);
        if (hn) {
            const uint32_t nxt = sb + (uint32_t)((chunk + 1) & 1) * BUF_BYTES;
            b_async(chunk + 1, nxt);
            set_meta(chunk + 1, nxt);
        }
        float v[8];
        pass_step(cur, SM_AHI, 0);
        if (hn) a_load8(0, v);
        pass_step(cur, SM_AHI, 1);
        if (hn) { a_finish(0, v); a_load8(1, v); }
        pass_step(cur, SM_AHI, 2);
        if (hn) { a_finish(1, v); a_load8(2, v); }
        pass_step(cur, SM_AHI, 3);
        if (hn) { a_finish(2, v); a_load8(3, v); }
        pass_step(cur, SM_ALO, 0);
        if (hn) { a_finish(3, v); a_load8(4, v); }
        pass_step(cur, SM_ALO, 1);
        if (hn) { a_finish(4, v); a_load8(5, v); }
        pass_step(cur, SM_ALO, 2);
        if (hn) { a_finish(5, v); a_load8(6, v); }
        pass_step(cur, SM_ALO, 3);
        if (hn) { a_finish(6, v); a_load8(7, v); a_finish(7, v); }
        if (hn) CP_WAIT0();
        __syncthreads();
    }

    // ---- epilogue ----
    float* ob = out + (size_t)b * COUT * HW + p0;
    const int mbase = mw * 64 + (lane >> 2);
    const int nbase2 = nw * 32 + (lane & 3) * 2;
#pragma unroll
    for (int mi = 0; mi < 4; mi++) {
#pragma unroll
        for (int ni = 0; ni < 4; ni++) {
            const int m = mbase + mi * 16;
            const int n = nbase2 + ni * 8;
            ob[(size_t)n * HW + m]           = acc[mi][ni][0];
            ob[(size_t)(n + 1) * HW + m]     = acc[mi][ni][1];
            ob[(size_t)n * HW + m + 8]       = acc[mi][ni][2];
            ob[(size_t)(n + 1) * HW + m + 8] = acc[mi][ni][3];
        }
    }
}

// ---------------------------------------------------------------------------
extern "C" void kernel_launch(void* const* d_in, const int* in_sizes, int n_in,
                              void* d_out, int out_size)
{
    (void)in_sizes; (void)n_in; (void)out_size;
    const float* x      = (const float*)d_in[0];
    const float* w_off  = (const float*)d_in[1];
    const float* b_off  = (const float*)d_in[2];
    const float* w_conv = (const float*)d_in[3];
    float* out = (float*)d_out;

    cudaFuncSetAttribute(mma_kernel,
                         cudaFuncAttributeMaxDynamicSharedMemorySize, SMEM_TOTAL);
    cudaFuncSetAttribute(offset_mma_kernel,
                         cudaFuncAttributeMaxDynamicSharedMemorySize, OSMEM_TOTAL);

    prepack_kernel<<<((COUT + 32) * KTOT + 255) / 256, 256>>>(w_conv, w_off);
    offset_mma_kernel<<<128, 256, OSMEM_TOTAL>>>(x, b_off);
    mma_kernel<<<128, 512, SMEM_TOTAL>>>(x, out);
}

// round 7
// speedup vs baseline: 1.4798x; 1.1829x over previous
#include <cuda_runtime.h>
#include <cuda_bf16.h>
#include <cuda_fp16.h>
#include <cstdint>

// Problem constants
#define BATCH 4
#define CIN   256
#define COUT  256
#define HH    64
#define WW    64
#define HW    4096
#define NTAP  9
#define KTOT  2304        // tap-major: k = tap*256 + c
#define NCHUNK 36         // 9 taps * 4 chunks of 64 channels

// ---------------- scratch ----------------
__device__ int4   g_idx[BATCH * NTAP * HW];
__device__ float4 g_wt [BATCH * NTAP * HW];
__device__ __half        g_bf[COUT * KTOT];   // w_conv fp16 [n][k], k = tap*256 + c
__device__ __nv_bfloat16 g_oh[32 * KTOT];     // w_off bf16 hi [n(27->32)][k]
__device__ __nv_bfloat16 g_ol[32 * KTOT];     // w_off bf16 lo

// ---------------- helpers ----------------
__device__ __forceinline__ uint32_t smem_u32(const void* p) {
    uint32_t a;
    asm("{ .reg .u64 t; cvta.to.shared.u64 t, %1; cvt.u32.u64 %0, t; }" : "=r"(a) : "l"(p));
    return a;
}
__device__ __forceinline__ void ldm_x4(uint32_t* r, uint32_t addr) {
    asm volatile("ldmatrix.sync.aligned.m8n8.x4.shared.b16 {%0,%1,%2,%3}, [%4];"
                 : "=r"(r[0]), "=r"(r[1]), "=r"(r[2]), "=r"(r[3]) : "r"(addr));
}
__device__ __forceinline__ void mma_bf16(float* c, const uint32_t* a, const uint32_t* b) {
    asm volatile(
        "mma.sync.aligned.m16n8k16.row.col.f32.bf16.bf16.f32 "
        "{%0,%1,%2,%3}, {%4,%5,%6,%7}, {%8,%9}, {%0,%1,%2,%3};"
        : "+f"(c[0]), "+f"(c[1]), "+f"(c[2]), "+f"(c[3])
        : "r"(a[0]), "r"(a[1]), "r"(a[2]), "r"(a[3]), "r"(b[0]), "r"(b[1]));
}
__device__ __forceinline__ void mma_fp16(float* c, const uint32_t* a, const uint32_t* b) {
    asm volatile(
        "mma.sync.aligned.m16n8k16.row.col.f32.f16.f16.f32 "
        "{%0,%1,%2,%3}, {%4,%5,%6,%7}, {%8,%9}, {%0,%1,%2,%3};"
        : "+f"(c[0]), "+f"(c[1]), "+f"(c[2]), "+f"(c[3])
        : "r"(a[0]), "r"(a[1]), "r"(a[2]), "r"(a[3]), "r"(b[0]), "r"(b[1]));
}
__device__ __forceinline__ void cpasync16(uint32_t dst, const void* src) {
    asm volatile("cp.async.cg.shared.global [%0], [%1], 16;" :: "r"(dst), "l"(src));
}
#define CP_COMMIT() asm volatile("cp.async.commit_group;")
#define CP_WAIT0()  asm volatile("cp.async.wait_group 0;" ::: "memory")

__device__ __forceinline__ uint32_t pack_bf16x2(float v0, float v1,
                                                uint32_t& lo_out) {
    const __nv_bfloat16 h0 = __float2bfloat16_rn(v0);
    const __nv_bfloat16 h1 = __float2bfloat16_rn(v1);
    const __nv_bfloat16 l0 = __float2bfloat16_rn(v0 - __bfloat162float(h0));
    const __nv_bfloat16 l1 = __float2bfloat16_rn(v1 - __bfloat162float(h1));
    lo_out = (uint32_t)__bfloat16_as_ushort(l0) | ((uint32_t)__bfloat16_as_ushort(l1) << 16);
    return (uint32_t)__bfloat16_as_ushort(h0) | ((uint32_t)__bfloat16_as_ushort(h1) << 16);
}
__device__ __forceinline__ uint32_t pack_f16x2_single(float v0, float v1) {
    const __half h0 = __float2half_rn(v0);
    const __half h1 = __float2half_rn(v1);
    return (uint32_t)__half_as_ushort(h0) | ((uint32_t)__half_as_ushort(h1) << 16);
}

// ---------------------------------------------------------------------------
// Stage 0: prepack w_conv (fp16) + w_off (bf16 hi/lo), tap-major
// ---------------------------------------------------------------------------
__global__ __launch_bounds__(256)
void prepack_kernel(const float* __restrict__ w_conv,
                    const float* __restrict__ w_off)
{
    const int i = blockIdx.x * 256 + threadIdx.x;
    if (i < COUT * KTOT) {
        const int n = i / KTOT, k = i % KTOT;
        const int tap = k >> 8, c = k & 255;
        g_bf[i] = __float2half_rn(w_conv[(n * CIN + c) * 9 + tap]);
    } else if (i < (COUT + 32) * KTOT) {
        const int j = i - COUT * KTOT;
        const int n = j / KTOT, k = j % KTOT;
        const int tap = k >> 8, c = k & 255;
        const float w = (n < 27) ? w_off[(n * CIN + c) * 9 + tap] : 0.f;
        const __nv_bfloat16 h = __float2bfloat16_rn(w);
        g_oh[j] = h;
        g_ol[j] = __float2bfloat16_rn(w - __bfloat162float(h));
    }
}

// ---------------------------------------------------------------------------
// Stage 1: offset conv on tensor cores (M=128/CTA, N=32, K=2304) + epilogue
// producing bilinear corner indices/weights.  (3-term bf16, unchanged)
// ---------------------------------------------------------------------------
#define OROWB 144
#define OS_AHI 0
#define OS_ALO (128 * OROWB)
#define OS_BHI (2 * 128 * OROWB)
#define OS_BLO (OS_BHI + 32 * OROWB)
#define OBUF   (OS_BLO + 32 * OROWB)          // 46080
#define OS_ACC (2 * OBUF)                     // 92160
#define OSMEM_TOTAL (OS_ACC + 128 * 33 * 4)   // 109056

__global__ __launch_bounds__(256, 1)
void offset_mma_kernel(const float* __restrict__ x,
                       const float* __restrict__ b_off)
{
    extern __shared__ char smem[];
    const uint32_t sb = smem_u32(smem);
    const int t    = threadIdx.x;
    const int lane = t & 31;
    const int wid  = t >> 5;
    const int b    = blockIdx.x >> 5;
    const int p0   = (blockIdx.x & 31) * 128;

    const float* xb = x + (size_t)b * CIN * HW;

    const int am = t & 127;
    const int ah = t >> 7;
    const int ph = (p0 + am) >> 6;
    const int pw = (p0 + am) & 63;

    const uint32_t a_row  = (uint32_t)(wid * 16 + (lane & 15));
    const uint32_t a_colb = (uint32_t)((lane >> 4) * 16);
    const uint32_t b_row  = (uint32_t)((lane & 7) + ((lane >> 4) << 3));
    const uint32_t b_colb = (uint32_t)(((lane >> 3) & 1) * 16);

    float acc[4][4];
#pragma unroll
    for (int ni = 0; ni < 4; ni++)
#pragma unroll
        for (int j = 0; j < 4; j++) acc[ni][j] = 0.f;

    auto build_a = [&](int chunk, uint32_t base) {
        const int tap = chunk >> 2;
        const int c0  = (chunk & 3) * 64;
        const int yy = ph - 1 + tap / 3;
        const int xx = pw - 1 + tap % 3;
        const bool ok = (yy >= 0) && (yy < HH) && (xx >= 0) && (xx < WW);
        const int sidx = ok ? (yy * WW + xx) : 0;
        const float* xc = xb + (size_t)(c0 + ah * 32) * HW + sidx;
#pragma unroll
        for (int jj = 0; jj < 16; jj++) {
            const float v0 = ok ? __ldg(xc + (size_t)(2 * jj) * HW) : 0.f;
            const float v1 = ok ? __ldg(xc + (size_t)(2 * jj + 1) * HW) : 0.f;
            uint32_t lo2, hi2 = pack_bf16x2(v0, v1, lo2);
            const uint32_t bo = (uint32_t)(am * OROWB + (ah * 32 + 2 * jj) * 2);
            asm volatile("st.shared.b32 [%0], %1;" :: "r"(base + OS_AHI + bo), "r"(hi2) : "memory");
            asm volatile("st.shared.b32 [%0], %1;" :: "r"(base + OS_ALO + bo), "r"(lo2) : "memory");
        }
    };
    auto build_b = [&](int chunk, uint32_t base) {
        const int tap = chunk >> 2;
        const int c0  = (chunk & 3) * 64;
        const int n = t >> 3, vw = t & 7;
        const size_t gofs = (size_t)n * KTOT + tap * 256 + c0 + vw * 8;
        const uint32_t bo = (uint32_t)(n * OROWB + vw * 16);
        cpasync16(base + OS_BHI + bo, g_oh + gofs);
        cpasync16(base + OS_BLO + bo, g_ol + gofs);
        CP_COMMIT();
    };
    auto compute = [&](uint32_t base) {
        const uint32_t Ah = base + OS_AHI, Al = base + OS_ALO;
        const uint32_t Bh = base + OS_BHI, Bl = base + OS_BLO;
#pragma unroll
        for (int s = 0; s < 4; s++) {
            uint32_t af[4];
            ldm_x4(af, Ah + a_row * OROWB + a_colb + s * 32);
            uint32_t bhf[4][2], blf[4][2];
#pragma unroll
            for (int np = 0; np < 2; np++) {
                uint32_t r[4];
                ldm_x4(r, Bh + (b_row + np * 16) * OROWB + b_colb + s * 32);
                bhf[np * 2][0] = r[0]; bhf[np * 2][1] = r[1];
                bhf[np * 2 + 1][0] = r[2]; bhf[np * 2 + 1][1] = r[3];
                ldm_x4(r, Bl + (b_row + np * 16) * OROWB + b_colb + s * 32);
                blf[np * 2][0] = r[0]; blf[np * 2][1] = r[1];
                blf[np * 2 + 1][0] = r[2]; blf[np * 2 + 1][1] = r[3];
            }
#pragma unroll
            for (int ni = 0; ni < 4; ni++) {
                mma_bf16(acc[ni], af, bhf[ni]);
                mma_bf16(acc[ni], af, blf[ni]);
            }
        }
#pragma unroll
        for (int s = 0; s < 4; s++) {
            uint32_t af[4];
            ldm_x4(af, Al + a_row * OROWB + a_colb + s * 32);
            uint32_t bhf[4][2];
#pragma unroll
            for (int np = 0; np < 2; np++) {
                uint32_t r[4];
                ldm_x4(r, Bh + (b_row + np * 16) * OROWB + b_colb + s * 32);
                bhf[np * 2][0] = r[0]; bhf[np * 2][1] = r[1];
                bhf[np * 2 + 1][0] = r[2]; bhf[np * 2 + 1][1] = r[3];
            }
#pragma unroll
            for (int ni = 0; ni < 4; ni++)
                mma_bf16(acc[ni], af, bhf[ni]);
        }
    };

    build_b(0, sb);
    build_a(0, sb);
    CP_WAIT0();
    __syncthreads();
    for (int chunk = 0; chunk < NCHUNK; chunk++) {
        const uint32_t cur = sb + (uint32_t)(chunk & 1) * OBUF;
        if (chunk + 1 < NCHUNK) {
            const uint32_t nxt = sb + (uint32_t)((chunk + 1) & 1) * OBUF;
            build_b(chunk + 1, nxt);
            build_a(chunk + 1, nxt);
        }
        compute(cur);
        CP_WAIT0();
        __syncthreads();
    }

    float* sacc = reinterpret_cast<float*>(smem + OS_ACC);
    const int mb = wid * 16 + (lane >> 2);
    const int nb = (lane & 3) * 2;
#pragma unroll
    for (int ni = 0; ni < 4; ni++) {
        const int n = nb + ni * 8;
        sacc[mb * 33 + n]           = acc[ni][0];
        sacc[mb * 33 + n + 1]       = acc[ni][1];
        sacc[(mb + 8) * 33 + n]     = acc[ni][2];
        sacc[(mb + 8) * 33 + n + 1] = acc[ni][3];
    }
    __syncthreads();

    if (t < 128) {
        const int p = p0 + t;
        const int h = p >> 6, w = p & 63;
        const float* row = sacc + t * 33;
#pragma unroll
        for (int k = 0; k < NTAP; k++) {
            const float dy = row[2 * k]     + __ldg(b_off + 2 * k);
            const float dx = row[2 * k + 1] + __ldg(b_off + 2 * k + 1);
            const float mz = row[18 + k]    + __ldg(b_off + 18 + k);
            const float m  = 1.f / (1.f + expf(-mz));

            const float py = dy + (float)(h - 1 + k / 3);
            const float px = dx + (float)(w - 1 + k % 3);
            const float y0 = floorf(py);
            const float x0 = floorf(px);
            const float wy = py - y0;
            const float wx = px - x0;

            const float cy[2]  = { y0, y0 + 1.f };
            const float cx[2]  = { x0, x0 + 1.f };
            const float wyv[2] = { 1.f - wy, wy };
            const float wxv[2] = { 1.f - wx, wx };

            int   idxv[4];
            float wtv[4];
#pragma unroll
            for (int jy = 0; jy < 2; jy++) {
#pragma unroll
                for (int jx = 0; jx < 2; jx++) {
                    const float yc = cy[jy], xc = cx[jx];
                    const bool valid = (yc >= 0.f) && (yc <= (float)(HH - 1)) &&
                                       (xc >= 0.f) && (xc <= (float)(WW - 1));
                    const int yi = (int)fminf(fmaxf(yc, 0.f), (float)(HH - 1));
                    const int xi = (int)fminf(fmaxf(xc, 0.f), (float)(WW - 1));
                    const int j = jy * 2 + jx;
                    idxv[j] = yi * WW + xi;
                    wtv[j]  = valid ? (wyv[jy] * wxv[jx] * m) : 0.f;
                }
            }
            const int o = (b * NTAP + k) * HW + p;
            g_idx[o] = make_int4(idxv[0], idxv[1], idxv[2], idxv[3]);
            g_wt[o]  = make_float4(wtv[0], wtv[1], wtv[2], wtv[3]);
        }
    }
}

// ---------------------------------------------------------------------------
// Stage 2: implicit GEMM via mma.sync fp16, single-term (A fp16, B fp16).
// 128 pixels x 256 couts per CTA, 512 threads (16 warps, 2m x 8n).
// 4 MMA k-steps per chunk; next-chunk gather interleaved.
// ---------------------------------------------------------------------------
#define ROWB   144
#define SM_A   0
#define SM_B   (128 * ROWB)                   // 18432
#define BUF_BYTES (SM_B + 256 * ROWB)         // 55296
#define SMEM_TOTAL (2 * BUF_BYTES)            // 110592

__global__ __launch_bounds__(512, 1)
void mma_kernel(const float* __restrict__ x, float* __restrict__ out)
{
    extern __shared__ char smem[];
    const uint32_t sb = smem_u32(smem);
    const int t    = threadIdx.x;
    const int lane = t & 31;
    const int wid  = t >> 5;
    const int b    = blockIdx.x >> 5;
    const int p0   = (blockIdx.x & 31) * 128;

    const float* xb = x + (size_t)b * CIN * HW;

    const int am = t & 127;   // pixel
    const int aq = t >> 7;    // channel quarter (16 ch)

    const int mw = wid & 1;
    const int nw = wid >> 1;

    float acc[4][4][4];
#pragma unroll
    for (int mi = 0; mi < 4; mi++)
#pragma unroll
        for (int ni = 0; ni < 4; ni++)
#pragma unroll
            for (int j = 0; j < 4; j++) acc[mi][ni][j] = 0.f;

    const uint32_t a_row  = (uint32_t)(mw * 64 + (lane & 15));
    const uint32_t a_colb = (uint32_t)((lane >> 4) * 16);
    const uint32_t b_row  = (uint32_t)(nw * 32 + (lane & 7) + ((lane >> 4) << 3));
    const uint32_t b_colb = (uint32_t)(((lane >> 3) & 1) * 16);

    // ---- next-chunk build state ----
    int4   idn;
    float4 wtn;
    const float* xcn = xb;
    uint32_t nbase = sb;

    auto set_meta = [&](int chunk, uint32_t base) {
        const int tap = chunk >> 2;
        const int c0  = (chunk & 3) * 64;
        const int off = (b * NTAP + tap) * HW + p0 + am;
        idn = g_idx[off];
        wtn = g_wt[off];
        xcn = xb + (size_t)(c0 + aq * 16) * HW;
        nbase = base;
    };
    auto a_load8 = [&](int g, float* v) {
        const float* xp0 = xcn + (size_t)(2 * g) * HW;
        const float* xp1 = xp0 + HW;
        v[0] = __ldg(xp0 + idn.x); v[1] = __ldg(xp0 + idn.y);
        v[2] = __ldg(xp0 + idn.z); v[3] = __ldg(xp0 + idn.w);
        v[4] = __ldg(xp1 + idn.x); v[5] = __ldg(xp1 + idn.y);
        v[6] = __ldg(xp1 + idn.z); v[7] = __ldg(xp1 + idn.w);
    };
    auto a_finish = [&](int g, const float* v) {
        const float v0 = wtn.x * v[0] + wtn.y * v[1] + wtn.z * v[2] + wtn.w * v[3];
        const float v1 = wtn.x * v[4] + wtn.y * v[5] + wtn.z * v[6] + wtn.w * v[7];
        const uint32_t hi2 = pack_f16x2_single(v0, v1);
        const uint32_t bo = (uint32_t)(am * ROWB + (aq * 16 + 2 * g) * 2);
        asm volatile("st.shared.b32 [%0], %1;" :: "r"(nbase + SM_A + bo), "r"(hi2) : "memory");
    };
    auto b_async = [&](int chunk, uint32_t base) {
        const int tap = chunk >> 2;
        const int c0  = (chunk & 3) * 64;
#pragma unroll
        for (int q2 = 0; q2 < 4; q2++) {
            const int v2 = t + 512 * q2;      // 0..2047 over (n, 16B-vec)
            const int n = v2 >> 3, vw = v2 & 7;
            const size_t gofs = (size_t)n * KTOT + tap * 256 + c0 + vw * 8;
            const uint32_t bo = (uint32_t)(n * ROWB + vw * 16);
            cpasync16(base + SM_B + bo, g_bf + gofs);
        }
        CP_COMMIT();
    };

    auto pass_step = [&](uint32_t base, int s) {
        const uint32_t A = base + SM_A;
        const uint32_t B = base + SM_B;
        uint32_t bf[4][2];
#pragma unroll
        for (int np = 0; np < 2; np++) {
            uint32_t r[4];
            ldm_x4(r, B + (b_row + np * 16) * ROWB + b_colb + s * 32);
            bf[np * 2][0] = r[0]; bf[np * 2][1] = r[1];
            bf[np * 2 + 1][0] = r[2]; bf[np * 2 + 1][1] = r[3];
        }
#pragma unroll
        for (int mi = 0; mi < 4; mi++) {
            uint32_t af[4];
            ldm_x4(af, A + (a_row + mi * 16) * ROWB + a_colb + s * 32);
#pragma unroll
            for (int ni = 0; ni < 4; ni++)
                mma_fp16(acc[mi][ni], af, bf[ni]);
        }
    };

    // ---- prologue: build chunk 0 ----
    b_async(0, sb);
    set_meta(0, sb);
    {
        float v[8];
#pragma unroll
        for (int g = 0; g < 8; g++) { a_load8(g, v); a_finish(g, v); }
    }
    CP_WAIT0();
    __syncthreads();

    // ---- pipelined K loop ----
    for (int chunk = 0; chunk < NCHUNK; chunk++) {
        const uint32_t cur = sb + (uint32_t)(chunk & 1) * BUF_BYTES;
        const bool hn = (chunk + 1 < NCHUNK);
        if (hn) {
            const uint32_t nxt = sb + (uint32_t)((chunk + 1) & 1) * BUF_BYTES;
            b_async(chunk + 1, nxt);
            set_meta(chunk + 1, nxt);
        }
        float v0[8], v1[8];
        pass_step(cur, 0);
        if (hn) { a_load8(0, v0); a_load8(1, v1); }
        pass_step(cur, 1);
        if (hn) { a_finish(0, v0); a_load8(2, v0); a_finish(1, v1); a_load8(3, v1); }
        pass_step(cur, 2);
        if (hn) { a_finish(2, v0); a_load8(4, v0); a_finish(3, v1); a_load8(5, v1); }
        pass_step(cur, 3);
        if (hn) { a_finish(4, v0); a_load8(6, v0); a_finish(5, v1); a_load8(7, v1);
                  a_finish(6, v0); a_finish(7, v1); }
        if (hn) CP_WAIT0();
        __syncthreads();
    }

    // ---- epilogue ----
    float* ob = out + (size_t)b * COUT * HW + p0;
    const int mbase = mw * 64 + (lane >> 2);
    const int nbase2 = nw * 32 + (lane & 3) * 2;
#pragma unroll
    for (int mi = 0; mi < 4; mi++) {
#pragma unroll
        for (int ni = 0; ni < 4; ni++) {
            const int m = mbase + mi * 16;
            const int n = nbase2 + ni * 8;
            ob[(size_t)n * HW + m]           = acc[mi][ni][0];
            ob[(size_t)(n + 1) * HW + m]     = acc[mi][ni][1];
            ob[(size_t)n * HW + m + 8]       = acc[mi][ni][2];
            ob[(size_t)(n + 1) * HW + m + 8] = acc[mi][ni][3];
        }
    }
}

// ---------------------------------------------------------------------------
extern "C" void kernel_launch(void* const* d_in, const int* in_sizes, int n_in,
                              void* d_out, int out_size)
{
    (void)in_sizes; (void)n_in; (void)out_size;
    const float* x      = (const float*)d_in[0];
    const float* w_off  = (const float*)d_in[1];
    const float* b_off  = (const float*)d_in[2];
    const float* w_conv = (const float*)d_in[3];
    float* out = (float*)d_out;

    cudaFuncSetAttribute(mma_kernel,
                         cudaFuncAttributeMaxDynamicSharedMemorySize, SMEM_TOTAL);
    cudaFuncSetAttribute(offset_mma_kernel,
                         cudaFuncAttributeMaxDynamicSharedMemorySize, OSMEM_TOTAL);

    prepack_kernel<<<((COUT + 32) * KTOT + 255) / 256, 256>>>(w_conv, w_off);
    offset_mma_kernel<<<128, 256, OSMEM_TOTAL>>>(x, b_off);
    mma_kernel<<<128, 512, SMEM_TOTAL>>>(x, out);
}

// round 8
// speedup vs baseline: 1.7611x; 1.1901x over previous
#include <cuda_runtime.h>
#include <cuda_bf16.h>
#include <cuda_fp16.h>
#include <cstdint>

// Problem constants
#define BATCH 4
#define CIN   256
#define COUT  256
#define HH    64
#define WW    64
#define HW    4096
#define NTAP  9
#define KTOT  2304        // tap-major: k = tap*256 + c
#define NCHUNK 36         // 9 taps * 4 chunks of 64 channels

// ---------------- scratch ----------------
__device__ int4   g_idx[BATCH * NTAP * HW];
__device__ float4 g_wt [BATCH * NTAP * HW];
__device__ __half g_bf[COUT * KTOT];   // w_conv fp16 [n][k], k = tap*256 + c
__device__ __half g_of[32 * KTOT];     // w_off fp16 [n(27->32)][k]

// ---------------- helpers ----------------
__device__ __forceinline__ uint32_t smem_u32(const void* p) {
    uint32_t a;
    asm("{ .reg .u64 t; cvta.to.shared.u64 t, %1; cvt.u32.u64 %0, t; }" : "=r"(a) : "l"(p));
    return a;
}
__device__ __forceinline__ void ldm_x4(uint32_t* r, uint32_t addr) {
    asm volatile("ldmatrix.sync.aligned.m8n8.x4.shared.b16 {%0,%1,%2,%3}, [%4];"
                 : "=r"(r[0]), "=r"(r[1]), "=r"(r[2]), "=r"(r[3]) : "r"(addr));
}
__device__ __forceinline__ void mma_fp16(float* c, const uint32_t* a, const uint32_t* b) {
    asm volatile(
        "mma.sync.aligned.m16n8k16.row.col.f32.f16.f16.f32 "
        "{%0,%1,%2,%3}, {%4,%5,%6,%7}, {%8,%9}, {%0,%1,%2,%3};"
        : "+f"(c[0]), "+f"(c[1]), "+f"(c[2]), "+f"(c[3])
        : "r"(a[0]), "r"(a[1]), "r"(a[2]), "r"(a[3]), "r"(b[0]), "r"(b[1]));
}
__device__ __forceinline__ void cpasync16(uint32_t dst, const void* src) {
    asm volatile("cp.async.cg.shared.global [%0], [%1], 16;" :: "r"(dst), "l"(src));
}
#define CP_COMMIT() asm volatile("cp.async.commit_group;")
#define CP_WAIT0()  asm volatile("cp.async.wait_group 0;" ::: "memory")

__device__ __forceinline__ uint32_t pack_f16x2_single(float v0, float v1) {
    const __half h0 = __float2half_rn(v0);
    const __half h1 = __float2half_rn(v1);
    return (uint32_t)__half_as_ushort(h0) | ((uint32_t)__half_as_ushort(h1) << 16);
}

// ---------------------------------------------------------------------------
// Stage 0: prepack w_conv (fp16) + w_off (fp16), tap-major
// ---------------------------------------------------------------------------
__global__ __launch_bounds__(256)
void prepack_kernel(const float* __restrict__ w_conv,
                    const float* __restrict__ w_off)
{
    const int i = blockIdx.x * 256 + threadIdx.x;
    if (i < COUT * KTOT) {
        const int n = i / KTOT, k = i % KTOT;
        const int tap = k >> 8, c = k & 255;
        g_bf[i] = __float2half_rn(w_conv[(n * CIN + c) * 9 + tap]);
    } else if (i < (COUT + 32) * KTOT) {
        const int j = i - COUT * KTOT;
        const int n = j / KTOT, k = j % KTOT;
        const int tap = k >> 8, c = k & 255;
        g_of[j] = __float2half_rn((n < 27) ? w_off[(n * CIN + c) * 9 + tap] : 0.f);
    }
}

// ---------------------------------------------------------------------------
// Stage 1: offset conv, single-term fp16 on tensor cores.
// M=128/CTA, N=32, K=2304. 512 threads, 16 warps (8m x 2n), warp tile 16x16.
// Epilogue produces bilinear corner indices/weights into g_idx/g_wt.
// ---------------------------------------------------------------------------
#define OROWB 144
#define OS_A   0
#define OS_B   (128 * OROWB)                  // 18432
#define OBUF   (OS_B + 32 * OROWB)            // 23040
#define OS_ACC (2 * OBUF)                     // 46080
#define OSMEM_TOTAL (OS_ACC + 128 * 33 * 4)   // 62976

__global__ __launch_bounds__(512, 1)
void offset_mma_kernel(const float* __restrict__ x,
                       const float* __restrict__ b_off)
{
    extern __shared__ char smem[];
    const uint32_t sb = smem_u32(smem);
    const int t    = threadIdx.x;
    const int lane = t & 31;
    const int wid  = t >> 5;
    const int b    = blockIdx.x >> 5;
    const int p0   = (blockIdx.x & 31) * 128;

    const float* xb = x + (size_t)b * CIN * HW;

    // A-build: pixel = t&127, channel quarter = t>>7 (16 channels)
    const int am = t & 127;
    const int aq = t >> 7;
    const int ph = (p0 + am) >> 6;
    const int pw = (p0 + am) & 63;

    // compute: 16 warps = 8m x 2n
    const int mw = wid & 7;
    const int nw = wid >> 3;

    const uint32_t a_row  = (uint32_t)(mw * 16 + (lane & 15));
    const uint32_t a_colb = (uint32_t)((lane >> 4) * 16);
    const uint32_t b_row  = (uint32_t)(nw * 16 + (lane & 7) + ((lane >> 4) << 3));
    const uint32_t b_colb = (uint32_t)(((lane >> 3) & 1) * 16);

    float acc[2][4];
#pragma unroll
    for (int ni = 0; ni < 2; ni++)
#pragma unroll
        for (int j = 0; j < 4; j++) acc[ni][j] = 0.f;

    // next-chunk gather state
    const float* xcn = xb;
    bool okn = false;
    uint32_t nbase = sb;

    auto set_meta = [&](int chunk, uint32_t base) {
        const int tap = chunk >> 2;
        const int c0  = (chunk & 3) * 64;
        const int yy = ph - 1 + tap / 3;
        const int xx = pw - 1 + tap % 3;
        okn = (yy >= 0) && (yy < HH) && (xx >= 0) && (xx < WW);
        xcn = xb + (size_t)(c0 + aq * 16) * HW + (okn ? (yy * WW + xx) : 0);
        nbase = base;
    };
    auto a_load2 = [&](int g, float* v) {
        v[0] = okn ? __ldg(xcn + (size_t)(2 * g) * HW) : 0.f;
        v[1] = okn ? __ldg(xcn + (size_t)(2 * g + 1) * HW) : 0.f;
    };
    auto a_finish = [&](int g, const float* v) {
        const uint32_t hi2 = pack_f16x2_single(v[0], v[1]);
        const uint32_t bo = (uint32_t)(am * OROWB + (aq * 16 + 2 * g) * 2);
        asm volatile("st.shared.b32 [%0], %1;" :: "r"(nbase + OS_A + bo), "r"(hi2) : "memory");
    };
    auto b_async = [&](int chunk, uint32_t base) {
        if (t < 256) {
            const int tap = chunk >> 2;
            const int c0  = (chunk & 3) * 64;
            const int n = t >> 3, vw = t & 7;   // 32 n x 8 vec16B
            const size_t gofs = (size_t)n * KTOT + tap * 256 + c0 + vw * 8;
            const uint32_t bo = (uint32_t)(n * OROWB + vw * 16);
            cpasync16(base + OS_B + bo, g_of + gofs);
        }
        CP_COMMIT();
    };
    auto pass_step = [&](uint32_t base, int s) {
        uint32_t bf[2][2];
        {
            uint32_t r[4];
            ldm_x4(r, base + OS_B + b_row * OROWB + b_colb + s * 32);
            bf[0][0] = r[0]; bf[0][1] = r[1];
            bf[1][0] = r[2]; bf[1][1] = r[3];
        }
        uint32_t af[4];
        ldm_x4(af, base + OS_A + a_row * OROWB + a_colb + s * 32);
#pragma unroll
        for (int ni = 0; ni < 2; ni++)
            mma_fp16(acc[ni], af, bf[ni]);
    };

    // prologue
    b_async(0, sb);
    set_meta(0, sb);
    {
        float v[2];
#pragma unroll
        for (int g = 0; g < 8; g++) { a_load2(g, v); a_finish(g, v); }
    }
    CP_WAIT0();
    __syncthreads();

    for (int chunk = 0; chunk < NCHUNK; chunk++) {
        const uint32_t cur = sb + (uint32_t)(chunk & 1) * OBUF;
        const bool hn = (chunk + 1 < NCHUNK);
        if (hn) {
            const uint32_t nxt = sb + (uint32_t)((chunk + 1) & 1) * OBUF;
            b_async(chunk + 1, nxt);
            set_meta(chunk + 1, nxt);
        }
        float v0[2], v1[2];
        pass_step(cur, 0);
        if (hn) { a_load2(0, v0); a_load2(1, v1); }
        pass_step(cur, 1);
        if (hn) { a_finish(0, v0); a_load2(2, v0); a_finish(1, v1); a_load2(3, v1); }
        pass_step(cur, 2);
        if (hn) { a_finish(2, v0); a_load2(4, v0); a_finish(3, v1); a_load2(5, v1); }
        pass_step(cur, 3);
        if (hn) { a_finish(4, v0); a_load2(6, v0); a_finish(5, v1); a_load2(7, v1);
                  a_finish(6, v0); a_finish(7, v1); }
        if (hn) CP_WAIT0();
        __syncthreads();
    }

    // stash acc so each thread can read one pixel's 27 values
    float* sacc = reinterpret_cast<float*>(smem + OS_ACC);
    const int mb = mw * 16 + (lane >> 2);
    const int nb = nw * 16 + (lane & 3) * 2;
#pragma unroll
    for (int ni = 0; ni < 2; ni++) {
        const int n = nb + ni * 8;
        sacc[mb * 33 + n]           = acc[ni][0];
        sacc[mb * 33 + n + 1]       = acc[ni][1];
        sacc[(mb + 8) * 33 + n]     = acc[ni][2];
        sacc[(mb + 8) * 33 + n + 1] = acc[ni][3];
    }
    __syncthreads();

    if (t < 128) {
        const int p = p0 + t;
        const int h = p >> 6, w = p & 63;
        const float* row = sacc + t * 33;
#pragma unroll
        for (int k = 0; k < NTAP; k++) {
            const float dy = row[2 * k]     + __ldg(b_off + 2 * k);
            const float dx = row[2 * k + 1] + __ldg(b_off + 2 * k + 1);
            const float mz = row[18 + k]    + __ldg(b_off + 18 + k);
            const float m  = 1.f / (1.f + expf(-mz));

            const float py = dy + (float)(h - 1 + k / 3);
            const float px = dx + (float)(w - 1 + k % 3);
            const float y0 = floorf(py);
            const float x0 = floorf(px);
            const float wy = py - y0;
            const float wx = px - x0;

            const float cy[2]  = { y0, y0 + 1.f };
            const float cx[2]  = { x0, x0 + 1.f };
            const float wyv[2] = { 1.f - wy, wy };
            const float wxv[2] = { 1.f - wx, wx };

            int   idxv[4];
            float wtv[4];
#pragma unroll
            for (int jy = 0; jy < 2; jy++) {
#pragma unroll
                for (int jx = 0; jx < 2; jx++) {
                    const float yc = cy[jy], xc = cx[jx];
                    const bool valid = (yc >= 0.f) && (yc <= (float)(HH - 1)) &&
                                       (xc >= 0.f) && (xc <= (float)(WW - 1));
                    const int yi = (int)fminf(fmaxf(yc, 0.f), (float)(HH - 1));
                    const int xi = (int)fminf(fmaxf(xc, 0.f), (float)(WW - 1));
                    const int j = jy * 2 + jx;
                    idxv[j] = yi * WW + xi;
                    wtv[j]  = valid ? (wyv[jy] * wxv[jx] * m) : 0.f;
                }
            }
            const int o = (b * NTAP + k) * HW + p;
            g_idx[o] = make_int4(idxv[0], idxv[1], idxv[2], idxv[3]);
            g_wt[o]  = make_float4(wtv[0], wtv[1], wtv[2], wtv[3]);
        }
    }
}

// ---------------------------------------------------------------------------
// Stage 2: implicit GEMM via mma.sync fp16, single-term (A fp16, B fp16).
// 128 pixels x 256 couts per CTA, 512 threads (16 warps, 2m x 8n).
// 4 MMA k-steps per chunk; next-chunk gather interleaved.  (unchanged)
// ---------------------------------------------------------------------------
#define ROWB   144
#define SM_A   0
#define SM_B   (128 * ROWB)                   // 18432
#define BUF_BYTES (SM_B + 256 * ROWB)         // 55296
#define SMEM_TOTAL (2 * BUF_BYTES)            // 110592

__global__ __launch_bounds__(512, 1)
void mma_kernel(const float* __restrict__ x, float* __restrict__ out)
{
    extern __shared__ char smem[];
    const uint32_t sb = smem_u32(smem);
    const int t    = threadIdx.x;
    const int lane = t & 31;
    const int wid  = t >> 5;
    const int b    = blockIdx.x >> 5;
    const int p0   = (blockIdx.x & 31) * 128;

    const float* xb = x + (size_t)b * CIN * HW;

    const int am = t & 127;   // pixel
    const int aq = t >> 7;    // channel quarter (16 ch)

    const int mw = wid & 1;
    const int nw = wid >> 1;

    float acc[4][4][4];
#pragma unroll
    for (int mi = 0; mi < 4; mi++)
#pragma unroll
        for (int ni = 0; ni < 4; ni++)
#pragma unroll
            for (int j = 0; j < 4; j++) acc[mi][ni][j] = 0.f;

    const uint32_t a_row  = (uint32_t)(mw * 64 + (lane & 15));
    const uint32_t a_colb = (uint32_t)((lane >> 4) * 16);
    const uint32_t b_row  = (uint32_t)(nw * 32 + (lane & 7) + ((lane >> 4) << 3));
    const uint32_t b_colb = (uint32_t)(((lane >> 3) & 1) * 16);

    int4   idn;
    float4 wtn;
    const float* xcn = xb;
    uint32_t nbase = sb;

    auto set_meta = [&](int chunk, uint32_t base) {
        const int tap = chunk >> 2;
        const int c0  = (chunk & 3) * 64;
        const int off = (b * NTAP + tap) * HW + p0 + am;
        idn = g_idx[off];
        wtn = g_wt[off];
        xcn = xb + (size_t)(c0 + aq * 16) * HW;
        nbase = base;
    };
    auto a_load8 = [&](int g, float* v) {
        const float* xp0 = xcn + (size_t)(2 * g) * HW;
        const float* xp1 = xp0 + HW;
        v[0] = __ldg(xp0 + idn.x); v[1] = __ldg(xp0 + idn.y);
        v[2] = __ldg(xp0 + idn.z); v[3] = __ldg(xp0 + idn.w);
        v[4] = __ldg(xp1 + idn.x); v[5] = __ldg(xp1 + idn.y);
        v[6] = __ldg(xp1 + idn.z); v[7] = __ldg(xp1 + idn.w);
    };
    auto a_finish = [&](int g, const float* v) {
        const float v0 = wtn.x * v[0] + wtn.y * v[1] + wtn.z * v[2] + wtn.w * v[3];
        const float v1 = wtn.x * v[4] + wtn.y * v[5] + wtn.z * v[6] + wtn.w * v[7];
        const uint32_t hi2 = pack_f16x2_single(v0, v1);
        const uint32_t bo = (uint32_t)(am * ROWB + (aq * 16 + 2 * g) * 2);
        asm volatile("st.shared.b32 [%0], %1;" :: "r"(nbase + SM_A + bo), "r"(hi2) : "memory");
    };
    auto b_async = [&](int chunk, uint32_t base) {
        const int tap = chunk >> 2;
        const int c0  = (chunk & 3) * 64;
#pragma unroll
        for (int q2 = 0; q2 < 4; q2++) {
            const int v2 = t + 512 * q2;
            const int n = v2 >> 3, vw = v2 & 7;
            const size_t gofs = (size_t)n * KTOT + tap * 256 + c0 + vw * 8;
            const uint32_t bo = (uint32_t)(n * ROWB + vw * 16);
            cpasync16(base + SM_B + bo, g_bf + gofs);
        }
        CP_COMMIT();
    };

    auto pass_step = [&](uint32_t base, int s) {
        const uint32_t A = base + SM_A;
        const uint32_t B = base + SM_B;
        uint32_t bf[4][2];
#pragma unroll
        for (int np = 0; np < 2; np++) {
            uint32_t r[4];
            ldm_x4(r, B + (b_row + np * 16) * ROWB + b_colb + s * 32);
            bf[np * 2][0] = r[0]; bf[np * 2][1] = r[1];
            bf[np * 2 + 1][0] = r[2]; bf[np * 2 + 1][1] = r[3];
        }
#pragma unroll
        for (int mi = 0; mi < 4; mi++) {
            uint32_t af[4];
            ldm_x4(af, A + (a_row + mi * 16) * ROWB + a_colb + s * 32);
#pragma unroll
            for (int ni = 0; ni < 4; ni++)
                mma_fp16(acc[mi][ni], af, bf[ni]);
        }
    };

    // prologue
    b_async(0, sb);
    set_meta(0, sb);
    {
        float v[8];
#pragma unroll
        for (int g = 0; g < 8; g++) { a_load8(g, v); a_finish(g, v); }
    }
    CP_WAIT0();
    __syncthreads();

    for (int chunk = 0; chunk < NCHUNK; chunk++) {
        const uint32_t cur = sb + (uint32_t)(chunk & 1) * BUF_BYTES;
        const bool hn = (chunk + 1 < NCHUNK);
        if (hn) {
            const uint32_t nxt = sb + (uint32_t)((chunk + 1) & 1) * BUF_BYTES;
            b_async(chunk + 1, nxt);
            set_meta(chunk + 1, nxt);
        }
        float v0[8], v1[8];
        pass_step(cur, 0);
        if (hn) { a_load8(0, v0); a_load8(1, v1); }
        pass_step(cur, 1);
        if (hn) { a_finish(0, v0); a_load8(2, v0); a_finish(1, v1); a_load8(3, v1); }
        pass_step(cur, 2);
        if (hn) { a_finish(2, v0); a_load8(4, v0); a_finish(3, v1); a_load8(5, v1); }
        pass_step(cur, 3);
        if (hn) { a_finish(4, v0); a_load8(6, v0); a_finish(5, v1); a_load8(7, v1);
                  a_finish(6, v0); a_finish(7, v1); }
        if (hn) CP_WAIT0();
        __syncthreads();
    }

    // epilogue
    float* ob = out + (size_t)b * COUT * HW + p0;
    const int mbase = mw * 64 + (lane >> 2);
    const int nbase2 = nw * 32 + (lane & 3) * 2;
#pragma unroll
    for (int mi = 0; mi < 4; mi++) {
#pragma unroll
        for (int ni = 0; ni < 4; ni++) {
            const int m = mbase + mi * 16;
            const int n = nbase2 + ni * 8;
            ob[(size_t)n * HW + m]           = acc[mi][ni][0];
            ob[(size_t)(n + 1) * HW + m]     = acc[mi][ni][1];
            ob[(size_t)n * HW + m + 8]       = acc[mi][ni][2];
            ob[(size_t)(n + 1) * HW + m + 8] = acc[mi][ni][3];
        }
    }
}

// ---------------------------------------------------------------------------
extern "C" void kernel_launch(void* const* d_in, const int* in_sizes, int n_in,
                              void* d_out, int out_size)
{
    (void)in_sizes; (void)n_in; (void)out_size;
    const float* x      = (const float*)d_in[0];
    const float* w_off  = (const float*)d_in[1];
    const float* b_off  = (const float*)d_in[2];
    const float* w_conv = (const float*)d_in[3];
    float* out = (float*)d_out;

    cudaFuncSetAttribute(mma_kernel,
                         cudaFuncAttributeMaxDynamicSharedMemorySize, SMEM_TOTAL);
    cudaFuncSetAttribute(offset_mma_kernel,
                         cudaFuncAttributeMaxDynamicSharedMemorySize, OSMEM_TOTAL);

    prepack_kernel<<<((COUT + 32) * KTOT + 255) / 256, 256>>>(w_conv, w_off);
    offset_mma_kernel<<<128, 512, OSMEM_TOTAL>>>(x, b_off);
    mma_kernel<<<128, 512, SMEM_TOTAL>>>(x, out);
}

// round 9
// speedup vs baseline: 1.8476x; 1.0491x over previous
#include <cuda_runtime.h>
#include <cuda_bf16.h>
#include <cuda_fp16.h>
#include <cstdint>

// Problem constants
#define BATCH 4
#define CIN   256
#define COUT  256
#define HH    64
#define WW    64
#define HW    4096
#define NTAP  9
#define KTOT  2304        // tap-major: k = tap*256 + c
#define NCH2  18          // merged chunks: 9 taps * 2 chunks of 128 channels

// ---------------- scratch ----------------
__device__ int4   g_idx[BATCH * NTAP * HW];
__device__ float4 g_wt [BATCH * NTAP * HW];
__device__ __half g_bf[COUT * KTOT];   // w_conv fp16 [n][k], k = tap*256 + c
__device__ __half g_of[32 * KTOT];     // w_off fp16 [n(27->32)][k]

// ---------------- helpers ----------------
__device__ __forceinline__ uint32_t smem_u32(const void* p) {
    uint32_t a;
    asm("{ .reg .u64 t; cvta.to.shared.u64 t, %1; cvt.u32.u64 %0, t; }" : "=r"(a) : "l"(p));
    return a;
}
__device__ __forceinline__ void ldm_x4(uint32_t* r, uint32_t addr) {
    asm volatile("ldmatrix.sync.aligned.m8n8.x4.shared.b16 {%0,%1,%2,%3}, [%4];"
                 : "=r"(r[0]), "=r"(r[1]), "=r"(r[2]), "=r"(r[3]) : "r"(addr));
}
__device__ __forceinline__ void mma_fp16(float* c, const uint32_t* a, const uint32_t* b) {
    asm volatile(
        "mma.sync.aligned.m16n8k16.row.col.f32.f16.f16.f32 "
        "{%0,%1,%2,%3}, {%4,%5,%6,%7}, {%8,%9}, {%0,%1,%2,%3};"
        : "+f"(c[0]), "+f"(c[1]), "+f"(c[2]), "+f"(c[3])
        : "r"(a[0]), "r"(a[1]), "r"(a[2]), "r"(a[3]), "r"(b[0]), "r"(b[1]));
}
__device__ __forceinline__ void cpasync16(uint32_t dst, const void* src) {
    asm volatile("cp.async.cg.shared.global [%0], [%1], 16;" :: "r"(dst), "l"(src));
}
#define CP_COMMIT() asm volatile("cp.async.commit_group;")
#define CP_WAIT0()  asm volatile("cp.async.wait_group 0;" ::: "memory")

__device__ __forceinline__ uint32_t pack_f16x2_single(float v0, float v1) {
    const __half h0 = __float2half_rn(v0);
    const __half h1 = __float2half_rn(v1);
    return (uint32_t)__half_as_ushort(h0) | ((uint32_t)__half_as_ushort(h1) << 16);
}

// ---------------------------------------------------------------------------
// Stage 0: prepack w_conv (fp16) + w_off (fp16), tap-major
// ---------------------------------------------------------------------------
__global__ __launch_bounds__(256)
void prepack_kernel(const float* __restrict__ w_conv,
                    const float* __restrict__ w_off)
{
    const int i = blockIdx.x * 256 + threadIdx.x;
    if (i < COUT * KTOT) {
        const int n = i / KTOT, k = i % KTOT;
        const int tap = k >> 8, c = k & 255;
        g_bf[i] = __float2half_rn(w_conv[(n * CIN + c) * 9 + tap]);
    } else if (i < (COUT + 32) * KTOT) {
        const int j = i - COUT * KTOT;
        const int n = j / KTOT, k = j % KTOT;
        const int tap = k >> 8, c = k & 255;
        g_of[j] = __float2half_rn((n < 27) ? w_off[(n * CIN + c) * 9 + tap] : 0.f);
    }
}

// ---------------------------------------------------------------------------
// Fused kernel: phase 1 = offset conv (fp16 mma) + bilinear meta epilogue;
//               phase 2 = main implicit GEMM consuming this CTA's own meta.
// Both phases: K-chunks of 128 channels (one tap), 18 chunks, double-buffered.
// ---------------------------------------------------------------------------
// Phase-1 smem
#define OROWB  272
#define OS_A   0
#define OS_B   (128 * OROWB)                  // 34816
#define OBUF   (OS_B + 32 * OROWB)            // 43520
#define OS_ACC (2 * OBUF)                     // 87040  (sacc: 128*33*4 = 16896)
// Phase-2 smem
#define ROWB   272
#define SM_A   0
#define SM_B   (128 * ROWB)                   // 34816
#define BUF_BYTES (SM_B + 256 * ROWB)         // 104448
#define SMEM_TOTAL (2 * BUF_BYTES)            // 208896

__global__ __launch_bounds__(512, 1)
void fused_kernel(const float* __restrict__ x,
                  const float* __restrict__ b_off,
                  float* __restrict__ out)
{
    extern __shared__ char smem[];
    const uint32_t sb = smem_u32(smem);
    const int t    = threadIdx.x;
    const int lane = t & 31;
    const int wid  = t >> 5;
    const int b    = blockIdx.x >> 5;
    const int p0   = (blockIdx.x & 31) * 128;

    const float* xb = x + (size_t)b * CIN * HW;

    const int am = t & 127;   // pixel
    const int aq = t >> 7;    // channel quarter (16 ch per 64-half)

    //======================= PHASE 1: offset conv =======================
    {
        const int ph = (p0 + am) >> 6;
        const int pw = (p0 + am) & 63;

        const int mw = wid & 7;   // 8 m-warps x 16 rows
        const int nw = wid >> 3;  // 2 n-warps x 16 couts

        const uint32_t a_row  = (uint32_t)(mw * 16 + (lane & 15));
        const uint32_t a_colb = (uint32_t)((lane >> 4) * 16);
        const uint32_t b_row  = (uint32_t)(nw * 16 + (lane & 7) + ((lane >> 4) << 3));
        const uint32_t b_colb = (uint32_t)(((lane >> 3) & 1) * 16);

        float acc[2][4];
#pragma unroll
        for (int ni = 0; ni < 2; ni++)
#pragma unroll
            for (int j = 0; j < 4; j++) acc[ni][j] = 0.f;

        const float* xcn = xb;
        bool okn = false;
        uint32_t nbase = sb;

        auto set_meta = [&](int chunk, uint32_t base) {
            const int tap = chunk >> 1;
            const int c0  = (chunk & 1) * 128;
            const int yy = ph - 1 + tap / 3;
            const int xx = pw - 1 + tap % 3;
            okn = (yy >= 0) && (yy < HH) && (xx >= 0) && (xx < WW);
            xcn = xb + (size_t)(c0 + aq * 16) * HW + (okn ? (yy * WW + xx) : 0);
            nbase = base;
        };
        auto a_load2 = [&](int g, float* v) {
            const int d = 2 * g + (g >= 8 ? 48 : 0);
            v[0] = okn ? __ldg(xcn + (size_t)d * HW) : 0.f;
            v[1] = okn ? __ldg(xcn + (size_t)(d + 1) * HW) : 0.f;
        };
        auto a_finish = [&](int g, const float* v) {
            const int col = aq * 16 + 2 * g + (g >= 8 ? 48 : 0);
            const uint32_t hi2 = pack_f16x2_single(v[0], v[1]);
            const uint32_t bo = (uint32_t)(am * OROWB + col * 2);
            asm volatile("st.shared.b32 [%0], %1;" :: "r"(nbase + OS_A + bo), "r"(hi2) : "memory");
        };
        auto b_async = [&](int chunk, uint32_t base) {
            const int tap = chunk >> 1;
            const int c0  = (chunk & 1) * 128;
            const int n = t >> 4, vw = t & 15;   // 32 n x 16 vec16B
            const size_t gofs = (size_t)n * KTOT + tap * 256 + c0 + vw * 8;
            const uint32_t bo = (uint32_t)(n * OROWB + vw * 16);
            cpasync16(base + OS_B + bo, g_of + gofs);
            CP_COMMIT();
        };
        auto pass_step = [&](uint32_t base, int s) {
            uint32_t bf[2][2];
            {
                uint32_t r[4];
                ldm_x4(r, base + OS_B + b_row * OROWB + b_colb + s * 32);
                bf[0][0] = r[0]; bf[0][1] = r[1];
                bf[1][0] = r[2]; bf[1][1] = r[3];
            }
            uint32_t af[4];
            ldm_x4(af, base + OS_A + a_row * OROWB + a_colb + s * 32);
#pragma unroll
            for (int ni = 0; ni < 2; ni++)
                mma_fp16(acc[ni], af, bf[ni]);
        };

        // prologue
        b_async(0, sb);
        set_meta(0, sb);
        {
            float v[2];
#pragma unroll
            for (int g = 0; g < 16; g++) { a_load2(g, v); a_finish(g, v); }
        }
        CP_WAIT0();
        __syncthreads();

        for (int chunk = 0; chunk < NCH2; chunk++) {
            const uint32_t cur = sb + (uint32_t)(chunk & 1) * OBUF;
            const bool hn = (chunk + 1 < NCH2);
            float v0[2], v1[2];
            if (hn) {
                const uint32_t nxt = sb + (uint32_t)((chunk + 1) & 1) * OBUF;
                b_async(chunk + 1, nxt);
                set_meta(chunk + 1, nxt);
                a_load2(0, v0); a_load2(1, v1);
            }
#pragma unroll
            for (int s = 0; s < 8; s++) {
                pass_step(cur, s);
                if (hn) {
                    if (s < 7) {
                        a_finish(2 * s, v0);     a_load2(2 * s + 2, v0);
                        a_finish(2 * s + 1, v1); a_load2(2 * s + 3, v1);
                    } else {
                        a_finish(14, v0); a_finish(15, v1);
                    }
                }
            }
            if (hn) CP_WAIT0();
            __syncthreads();
        }

        // stash acc so each thread reads one pixel's 27 outputs
        float* sacc = reinterpret_cast<float*>(smem + OS_ACC);
        const int mb = mw * 16 + (lane >> 2);
        const int nb = nw * 16 + (lane & 3) * 2;
#pragma unroll
        for (int ni = 0; ni < 2; ni++) {
            const int n = nb + ni * 8;
            sacc[mb * 33 + n]           = acc[ni][0];
            sacc[mb * 33 + n + 1]       = acc[ni][1];
            sacc[(mb + 8) * 33 + n]     = acc[ni][2];
            sacc[(mb + 8) * 33 + n + 1] = acc[ni][3];
        }
        __syncthreads();

        if (t < 128) {
            const int p = p0 + t;
            const int h = p >> 6, w = p & 63;
            const float* row = sacc + t * 33;
#pragma unroll
            for (int k = 0; k < NTAP; k++) {
                const float dy = row[2 * k]     + __ldg(b_off + 2 * k);
                const float dx = row[2 * k + 1] + __ldg(b_off + 2 * k + 1);
                const float mz = row[18 + k]    + __ldg(b_off + 18 + k);
                const float m  = 1.f / (1.f + expf(-mz));

                const float py = dy + (float)(h - 1 + k / 3);
                const float px = dx + (float)(w - 1 + k % 3);
                const float y0 = floorf(py);
                const float x0 = floorf(px);
                const float wy = py - y0;
                const float wx = px - x0;

                const float cy[2]  = { y0, y0 + 1.f };
                const float cx[2]  = { x0, x0 + 1.f };
                const float wyv[2] = { 1.f - wy, wy };
                const float wxv[2] = { 1.f - wx, wx };

                int   idxv[4];
                float wtv[4];
#pragma unroll
                for (int jy = 0; jy < 2; jy++) {
#pragma unroll
                    for (int jx = 0; jx < 2; jx++) {
                        const float yc = cy[jy], xc = cx[jx];
                        const bool valid = (yc >= 0.f) && (yc <= (float)(HH - 1)) &&
                                           (xc >= 0.f) && (xc <= (float)(WW - 1));
                        const int yi = (int)fminf(fmaxf(yc, 0.f), (float)(HH - 1));
                        const int xi = (int)fminf(fmaxf(xc, 0.f), (float)(WW - 1));
                        const int j = jy * 2 + jx;
                        idxv[j] = yi * WW + xi;
                        wtv[j]  = valid ? (wyv[jy] * wxv[jx] * m) : 0.f;
                    }
                }
                const int o = (b * NTAP + k) * HW + p;
                g_idx[o] = make_int4(idxv[0], idxv[1], idxv[2], idxv[3]);
                g_wt[o]  = make_float4(wtv[0], wtv[1], wtv[2], wtv[3]);
            }
        }
    }
    __syncthreads();   // meta written (global, same CTA) + smem free

    //======================= PHASE 2: main GEMM =======================
    {
        const int mw = wid & 1;   // 2 m-warps x 64 rows
        const int nw = wid >> 1;  // 8 n-warps x 32 couts

        float acc[4][4][4];
#pragma unroll
        for (int mi = 0; mi < 4; mi++)
#pragma unroll
            for (int ni = 0; ni < 4; ni++)
#pragma unroll
                for (int j = 0; j < 4; j++) acc[mi][ni][j] = 0.f;

        const uint32_t a_row  = (uint32_t)(mw * 64 + (lane & 15));
        const uint32_t a_colb = (uint32_t)((lane >> 4) * 16);
        const uint32_t b_row  = (uint32_t)(nw * 32 + (lane & 7) + ((lane >> 4) << 3));
        const uint32_t b_colb = (uint32_t)(((lane >> 3) & 1) * 16);

        int4   idn;
        float4 wtn;
        const float* xcn = xb;
        uint32_t nbase = sb;

        auto set_meta = [&](int chunk, uint32_t base, bool reload) {
            const int tap = chunk >> 1;
            const int c0  = (chunk & 1) * 128;
            if (reload) {
                const int off = (b * NTAP + tap) * HW + p0 + am;
                idn = g_idx[off];
                wtn = g_wt[off];
            }
            xcn = xb + (size_t)(c0 + aq * 16) * HW;
            nbase = base;
        };
        auto a_load8 = [&](int g, float* v) {
            const int d = 2 * g + (g >= 8 ? 48 : 0);
            const float* xp0 = xcn + (size_t)d * HW;
            const float* xp1 = xp0 + HW;
            v[0] = __ldg(xp0 + idn.x); v[1] = __ldg(xp0 + idn.y);
            v[2] = __ldg(xp0 + idn.z); v[3] = __ldg(xp0 + idn.w);
            v[4] = __ldg(xp1 + idn.x); v[5] = __ldg(xp1 + idn.y);
            v[6] = __ldg(xp1 + idn.z); v[7] = __ldg(xp1 + idn.w);
        };
        auto a_finish = [&](int g, const float* v) {
            const int col = aq * 16 + 2 * g + (g >= 8 ? 48 : 0);
            const float v0 = wtn.x * v[0] + wtn.y * v[1] + wtn.z * v[2] + wtn.w * v[3];
            const float v1 = wtn.x * v[4] + wtn.y * v[5] + wtn.z * v[6] + wtn.w * v[7];
            const uint32_t hi2 = pack_f16x2_single(v0, v1);
            const uint32_t bo = (uint32_t)(am * ROWB + col * 2);
            asm volatile("st.shared.b32 [%0], %1;" :: "r"(nbase + SM_A + bo), "r"(hi2) : "memory");
        };
        auto b_async = [&](int chunk, uint32_t base) {
            const int tap = chunk >> 1;
            const int c0  = (chunk & 1) * 128;
#pragma unroll
            for (int q2 = 0; q2 < 8; q2++) {
                const int v2 = t + 512 * q2;      // 0..4095 over (n, 16B-vec)
                const int n = v2 >> 4, vw = v2 & 15;
                const size_t gofs = (size_t)n * KTOT + tap * 256 + c0 + vw * 8;
                const uint32_t bo = (uint32_t)(n * ROWB + vw * 16);
                cpasync16(base + SM_B + bo, g_bf + gofs);
            }
            CP_COMMIT();
        };
        auto pass_step = [&](uint32_t base, int s) {
            const uint32_t A = base + SM_A;
            const uint32_t B = base + SM_B;
            uint32_t bf[4][2];
#pragma unroll
            for (int np = 0; np < 2; np++) {
                uint32_t r[4];
                ldm_x4(r, B + (b_row + np * 16) * ROWB + b_colb + s * 32);
                bf[np * 2][0] = r[0]; bf[np * 2][1] = r[1];
                bf[np * 2 + 1][0] = r[2]; bf[np * 2 + 1][1] = r[3];
            }
#pragma unroll
            for (int mi = 0; mi < 4; mi++) {
                uint32_t af[4];
                ldm_x4(af, A + (a_row + mi * 16) * ROWB + a_colb + s * 32);
#pragma unroll
                for (int ni = 0; ni < 4; ni++)
                    mma_fp16(acc[mi][ni], af, bf[ni]);
            }
        };

        // prologue
        b_async(0, sb);
        set_meta(0, sb, true);
        {
            float v[8];
#pragma unroll
            for (int g = 0; g < 16; g++) { a_load8(g, v); a_finish(g, v); }
        }
        CP_WAIT0();
        __syncthreads();

        for (int chunk = 0; chunk < NCH2; chunk++) {
            const uint32_t cur = sb + (uint32_t)(chunk & 1) * BUF_BYTES;
            const bool hn = (chunk + 1 < NCH2);
            float v0[8], v1[8];
            if (hn) {
                const uint32_t nxt = sb + (uint32_t)((chunk + 1) & 1) * BUF_BYTES;
                b_async(chunk + 1, nxt);
                set_meta(chunk + 1, nxt, (((chunk + 1) & 1) == 0));
                a_load8(0, v0); a_load8(1, v1);
            }
#pragma unroll
            for (int s = 0; s < 8; s++) {
                pass_step(cur, s);
                if (hn) {
                    if (s < 7) {
                        a_finish(2 * s, v0);     a_load8(2 * s + 2, v0);
                        a_finish(2 * s + 1, v1); a_load8(2 * s + 3, v1);
                    } else {
                        a_finish(14, v0); a_finish(15, v1);
                    }
                }
            }
            if (hn) CP_WAIT0();
            __syncthreads();
        }

        // epilogue
        float* ob = out + (size_t)b * COUT * HW + p0;
        const int mbase = mw * 64 + (lane >> 2);
        const int nbase2 = nw * 32 + (lane & 3) * 2;
#pragma unroll
        for (int mi = 0; mi < 4; mi++) {
#pragma unroll
            for (int ni = 0; ni < 4; ni++) {
                const int m = mbase + mi * 16;
                const int n = nbase2 + ni * 8;
                ob[(size_t)n * HW + m]           = acc[mi][ni][0];
                ob[(size_t)(n + 1) * HW + m]     = acc[mi][ni][1];
                ob[(size_t)n * HW + m + 8]       = acc[mi][ni][2];
                ob[(size_t)(n + 1) * HW + m + 8] = acc[mi][ni][3];
            }
        }
    }
}

// ---------------------------------------------------------------------------
extern "C" void kernel_launch(void* const* d_in, const int* in_sizes, int n_in,
                              void* d_out, int out_size)
{
    (void)in_sizes; (void)n_in; (void)out_size;
    const float* x      = (const float*)d_in[0];
    const float* w_off  = (const float*)d_in[1];
    const float* b_off  = (const float*)d_in[2];
    const float* w_conv = (const float*)d_in[3];
    float* out = (float*)d_out;

    cudaFuncSetAttribute(fused_kernel,
                         cudaFuncAttributeMaxDynamicSharedMemorySize, SMEM_TOTAL);

    prepack_kernel<<<((COUT + 32) * KTOT + 255) / 256, 256>>>(w_conv, w_off);
    fused_kernel<<<128, 512, SMEM_TOTAL>>>(x, b_off, out);
}

// round 10
// speedup vs baseline: 2.3079x; 1.2492x over previous
#include <cuda_runtime.h>
#include <cuda_bf16.h>
#include <cuda_fp16.h>
#include <cstdint>

// Problem constants
#define BATCH 4
#define CIN   256
#define CPAIR 128         // CIN/2 channel-pairs
#define COUT  256
#define HH    64
#define WW    64
#define HW    4096
#define NTAP  9
#define KTOT  2304        // tap-major: k = tap*256 + c
#define NCH2  18          // merged chunks: 9 taps * 2 chunks of 128 channels

// ---------------- scratch ----------------
__device__ int4     g_idx[BATCH * NTAP * HW];
__device__ float4   g_wt [BATCH * NTAP * HW];
__device__ __half   g_bf[COUT * KTOT];          // w_conv fp16 [n][k]
__device__ __half   g_of[32 * KTOT];            // w_off fp16 [n(27->32)][k]
__device__ uint32_t g_xh[BATCH * CPAIR * HW];   // x as half2 pairs [b][c2][p]

// ---------------- helpers ----------------
__device__ __forceinline__ uint32_t smem_u32(const void* p) {
    uint32_t a;
    asm("{ .reg .u64 t; cvta.to.shared.u64 t, %1; cvt.u32.u64 %0, t; }" : "=r"(a) : "l"(p));
    return a;
}
__device__ __forceinline__ void ldm_x4(uint32_t* r, uint32_t addr) {
    asm volatile("ldmatrix.sync.aligned.m8n8.x4.shared.b16 {%0,%1,%2,%3}, [%4];"
                 : "=r"(r[0]), "=r"(r[1]), "=r"(r[2]), "=r"(r[3]) : "r"(addr));
}
__device__ __forceinline__ void mma_fp16(float* c, const uint32_t* a, const uint32_t* b) {
    asm volatile(
        "mma.sync.aligned.m16n8k16.row.col.f32.f16.f16.f32 "
        "{%0,%1,%2,%3}, {%4,%5,%6,%7}, {%8,%9}, {%0,%1,%2,%3};"
        : "+f"(c[0]), "+f"(c[1]), "+f"(c[2]), "+f"(c[3])
        : "r"(a[0]), "r"(a[1]), "r"(a[2]), "r"(a[3]), "r"(b[0]), "r"(b[1]));
}
__device__ __forceinline__ void cpasync16(uint32_t dst, const void* src) {
    asm volatile("cp.async.cg.shared.global [%0], [%1], 16;" :: "r"(dst), "l"(src));
}
#define CP_COMMIT() asm volatile("cp.async.commit_group;")
#define CP_WAIT0()  asm volatile("cp.async.wait_group 0;" ::: "memory")

__device__ __forceinline__ uint32_t pack_f16x2_single(float v0, float v1) {
    const __half h0 = __float2half_rn(v0);
    const __half h1 = __float2half_rn(v1);
    return (uint32_t)__half_as_ushort(h0) | ((uint32_t)__half_as_ushort(h1) << 16);
}
__device__ __forceinline__ void sts64(uint32_t addr, uint32_t r0, uint32_t r1) {
    asm volatile("st.shared.v2.b32 [%0], {%1, %2};" :: "r"(addr), "r"(r0), "r"(r1) : "memory");
}

// ---------------------------------------------------------------------------
// Stage 0a: prepack weights (fp16, tap-major)
// ---------------------------------------------------------------------------
__global__ __launch_bounds__(256)
void prepack_kernel(const float* __restrict__ w_conv,
                    const float* __restrict__ w_off)
{
    const int i = blockIdx.x * 256 + threadIdx.x;
    if (i < COUT * KTOT) {
        const int n = i / KTOT, k = i % KTOT;
        const int tap = k >> 8, c = k & 255;
        g_bf[i] = __float2half_rn(w_conv[(n * CIN + c) * 9 + tap]);
    } else if (i < (COUT + 32) * KTOT) {
        const int j = i - COUT * KTOT;
        const int n = j / KTOT, k = j % KTOT;
        const int tap = k >> 8, c = k & 255;
        g_of[j] = __float2half_rn((n < 27) ? w_off[(n * CIN + c) * 9 + tap] : 0.f);
    }
}

// ---------------------------------------------------------------------------
// Stage 0b: prepack x -> fp16 half2 channel pairs
// ---------------------------------------------------------------------------
__global__ __launch_bounds__(256)
void prepack_x_kernel(const float* __restrict__ x)
{
    const int i = blockIdx.x * 256 + threadIdx.x;   // over BATCH*CPAIR*HW
    const int b  = i >> 19;           // / (CPAIR*HW)
    const int r  = i & 524287;
    const int c2 = r >> 12;
    const int p  = r & 4095;
    const float v0 = x[((size_t)b * CIN + 2 * c2) * HW + p];
    const float v1 = x[((size_t)b * CIN + 2 * c2 + 1) * HW + p];
    g_xh[i] = pack_f16x2_single(v0, v1);
}

// ---------------------------------------------------------------------------
// Fused kernel: phase 1 = offset conv (fp16 mma) + bilinear meta epilogue;
//               phase 2 = main implicit GEMM consuming this CTA's own meta.
// Gathers read half2 channel pairs (one LDG per 2 channels).
// ---------------------------------------------------------------------------
// Phase-1 smem
#define OROWB  272
#define OS_A   0
#define OS_B   (128 * OROWB)                  // 34816
#define OBUF   (OS_B + 32 * OROWB)            // 43520
#define OS_ACC (2 * OBUF)                     // 87040
// Phase-2 smem
#define ROWB   272
#define SM_A   0
#define SM_B   (128 * ROWB)                   // 34816
#define BUF_BYTES (SM_B + 256 * ROWB)         // 104448
#define SMEM_TOTAL (2 * BUF_BYTES)            // 208896

__global__ __launch_bounds__(512, 1)
void fused_kernel(const float* __restrict__ b_off,
                  float* __restrict__ out)
{
    extern __shared__ char smem[];
    const uint32_t sb = smem_u32(smem);
    const int t    = threadIdx.x;
    const int lane = t & 31;
    const int wid  = t >> 5;
    const int b    = blockIdx.x >> 5;
    const int p0   = (blockIdx.x & 31) * 128;

    const uint32_t* xhb = g_xh + (size_t)b * CPAIR * HW;

    const int am = t & 127;   // pixel
    const int aq = t >> 7;    // channel quarter (8 pairs per 32-pair half)

    //======================= PHASE 1: offset conv =======================
    {
        const int ph = (p0 + am) >> 6;
        const int pw = (p0 + am) & 63;

        const int mw = wid & 7;
        const int nw = wid >> 3;

        const uint32_t a_row  = (uint32_t)(mw * 16 + (lane & 15));
        const uint32_t a_colb = (uint32_t)((lane >> 4) * 16);
        const uint32_t b_row  = (uint32_t)(nw * 16 + (lane & 7) + ((lane >> 4) << 3));
        const uint32_t b_colb = (uint32_t)(((lane >> 3) & 1) * 16);

        float acc[2][4];
#pragma unroll
        for (int ni = 0; ni < 2; ni++)
#pragma unroll
            for (int j = 0; j < 4; j++) acc[ni][j] = 0.f;

        const uint32_t* xcn = xhb;
        bool okn = false;
        uint32_t nbase = sb;

        auto set_meta = [&](int chunk, uint32_t base) {
            const int tap = chunk >> 1;
            const int cp0 = (chunk & 1) * 64;
            const int yy = ph - 1 + tap / 3;
            const int xx = pw - 1 + tap % 3;
            okn = (yy >= 0) && (yy < HH) && (xx >= 0) && (xx < WW);
            xcn = xhb + (size_t)(cp0 + aq * 8) * HW + (okn ? (yy * WW + xx) : 0);
            nbase = base;
        };
        auto a_load1 = [&](int g, uint32_t* v) {
            const int d = g + (g >= 8 ? 24 : 0);
            v[0] = okn ? __ldg(xcn + (size_t)d * HW) : 0u;
        };
        auto a_finish2 = [&](int s, const uint32_t* v0, const uint32_t* v1) {
            const int colb = 32 * aq + 8 * s + (s >= 4 ? 96 : 0);
            sts64(nbase + OS_A + (uint32_t)(am * OROWB + colb), v0[0], v1[0]);
        };
        auto b_async = [&](int chunk, uint32_t base) {
            const int tap = chunk >> 1;
            const int c0  = (chunk & 1) * 128;
            const int n = t >> 4, vw = t & 15;
            const size_t gofs = (size_t)n * KTOT + tap * 256 + c0 + vw * 8;
            const uint32_t bo = (uint32_t)(n * OROWB + vw * 16);
            cpasync16(base + OS_B + bo, g_of + gofs);
            CP_COMMIT();
        };
        auto pass_step = [&](uint32_t base, int s) {
            uint32_t bf[2][2];
            {
                uint32_t r[4];
                ldm_x4(r, base + OS_B + b_row * OROWB + b_colb + s * 32);
                bf[0][0] = r[0]; bf[0][1] = r[1];
                bf[1][0] = r[2]; bf[1][1] = r[3];
            }
            uint32_t af[4];
            ldm_x4(af, base + OS_A + a_row * OROWB + a_colb + s * 32);
#pragma unroll
            for (int ni = 0; ni < 2; ni++)
                mma_fp16(acc[ni], af, bf[ni]);
        };

        // prologue
        b_async(0, sb);
        set_meta(0, sb);
        {
            uint32_t u0[1], u1[1];
#pragma unroll
            for (int s = 0; s < 8; s++) {
                a_load1(2 * s, u0); a_load1(2 * s + 1, u1);
                a_finish2(s, u0, u1);
            }
        }
        CP_WAIT0();
        __syncthreads();

        for (int chunk = 0; chunk < NCH2; chunk++) {
            const uint32_t cur = sb + (uint32_t)(chunk & 1) * OBUF;
            const bool hn = (chunk + 1 < NCH2);
            uint32_t v0[1], v1[1];
            if (hn) {
                const uint32_t nxt = sb + (uint32_t)((chunk + 1) & 1) * OBUF;
                b_async(chunk + 1, nxt);
                set_meta(chunk + 1, nxt);
                a_load1(0, v0); a_load1(1, v1);
            }
#pragma unroll
            for (int s = 0; s < 8; s++) {
                pass_step(cur, s);
                if (hn) {
                    if (s < 7) {
                        a_finish2(s, v0, v1);
                        a_load1(2 * s + 2, v0); a_load1(2 * s + 3, v1);
                    } else {
                        a_finish2(7, v0, v1);
                    }
                }
            }
            if (hn) CP_WAIT0();
            __syncthreads();
        }

        // stash acc so each thread reads one pixel's 27 outputs
        float* sacc = reinterpret_cast<float*>(smem + OS_ACC);
        const int mb = mw * 16 + (lane >> 2);
        const int nb = nw * 16 + (lane & 3) * 2;
#pragma unroll
        for (int ni = 0; ni < 2; ni++) {
            const int n = nb + ni * 8;
            sacc[mb * 33 + n]           = acc[ni][0];
            sacc[mb * 33 + n + 1]       = acc[ni][1];
            sacc[(mb + 8) * 33 + n]     = acc[ni][2];
            sacc[(mb + 8) * 33 + n + 1] = acc[ni][3];
        }
        __syncthreads();

        if (t < 128) {
            const int p = p0 + t;
            const int h = p >> 6, w = p & 63;
            const float* row = sacc + t * 33;
#pragma unroll
            for (int k = 0; k < NTAP; k++) {
                const float dy = row[2 * k]     + __ldg(b_off + 2 * k);
                const float dx = row[2 * k + 1] + __ldg(b_off + 2 * k + 1);
                const float mz = row[18 + k]    + __ldg(b_off + 18 + k);
                const float m  = 1.f / (1.f + expf(-mz));

                const float py = dy + (float)(h - 1 + k / 3);
                const float px = dx + (float)(w - 1 + k % 3);
                const float y0 = floorf(py);
                const float x0 = floorf(px);
                const float wy = py - y0;
                const float wx = px - x0;

                const float cy[2]  = { y0, y0 + 1.f };
                const float cx[2]  = { x0, x0 + 1.f };
                const float wyv[2] = { 1.f - wy, wy };
                const float wxv[2] = { 1.f - wx, wx };

                int   idxv[4];
                float wtv[4];
#pragma unroll
                for (int jy = 0; jy < 2; jy++) {
#pragma unroll
                    for (int jx = 0; jx < 2; jx++) {
                        const float yc = cy[jy], xc = cx[jx];
                        const bool valid = (yc >= 0.f) && (yc <= (float)(HH - 1)) &&
                                           (xc >= 0.f) && (xc <= (float)(WW - 1));
                        const int yi = (int)fminf(fmaxf(yc, 0.f), (float)(HH - 1));
                        const int xi = (int)fminf(fmaxf(xc, 0.f), (float)(WW - 1));
                        const int j = jy * 2 + jx;
                        idxv[j] = yi * WW + xi;
                        wtv[j]  = valid ? (wyv[jy] * wxv[jx] * m) : 0.f;
                    }
                }
                const int o = (b * NTAP + k) * HW + p;
                g_idx[o] = make_int4(idxv[0], idxv[1], idxv[2], idxv[3]);
                g_wt[o]  = make_float4(wtv[0], wtv[1], wtv[2], wtv[3]);
            }
        }
    }
    __syncthreads();   // meta written (global, same CTA) + smem free

    //======================= PHASE 2: main GEMM =======================
    {
        const int mw = wid & 1;
        const int nw = wid >> 1;

        float acc[4][4][4];
#pragma unroll
        for (int mi = 0; mi < 4; mi++)
#pragma unroll
            for (int ni = 0; ni < 4; ni++)
#pragma unroll
                for (int j = 0; j < 4; j++) acc[mi][ni][j] = 0.f;

        const uint32_t a_row  = (uint32_t)(mw * 64 + (lane & 15));
        const uint32_t a_colb = (uint32_t)((lane >> 4) * 16);
        const uint32_t b_row  = (uint32_t)(nw * 32 + (lane & 7) + ((lane >> 4) << 3));
        const uint32_t b_colb = (uint32_t)(((lane >> 3) & 1) * 16);

        int4   idn;
        float4 wtn;
        const uint32_t* xcn = xhb;
        uint32_t nbase = sb;

        auto set_meta = [&](int chunk, uint32_t base, bool reload) {
            const int tap = chunk >> 1;
            const int cp0 = (chunk & 1) * 64;
            if (reload) {
                const int off = (b * NTAP + tap) * HW + p0 + am;
                idn = g_idx[off];
                wtn = g_wt[off];
            }
            xcn = xhb + (size_t)(cp0 + aq * 8) * HW;
            nbase = base;
        };
        auto a_load4 = [&](int g, uint32_t* v) {
            const int d = g + (g >= 8 ? 24 : 0);
            const uint32_t* xp = xcn + (size_t)d * HW;
            v[0] = __ldg(xp + idn.x); v[1] = __ldg(xp + idn.y);
            v[2] = __ldg(xp + idn.z); v[3] = __ldg(xp + idn.w);
        };
        auto dotpack = [&](const uint32_t* v) -> uint32_t {
            const float2 f0 = __half22float2(*reinterpret_cast<const __half2*>(&v[0]));
            const float2 f1 = __half22float2(*reinterpret_cast<const __half2*>(&v[1]));
            const float2 f2 = __half22float2(*reinterpret_cast<const __half2*>(&v[2]));
            const float2 f3 = __half22float2(*reinterpret_cast<const __half2*>(&v[3]));
            const float a0 = wtn.x * f0.x + wtn.y * f1.x + wtn.z * f2.x + wtn.w * f3.x;
            const float a1 = wtn.x * f0.y + wtn.y * f1.y + wtn.z * f2.y + wtn.w * f3.y;
            return pack_f16x2_single(a0, a1);
        };
        auto a_finish2 = [&](int s, const uint32_t* v0, const uint32_t* v1) {
            const int colb = 32 * aq + 8 * s + (s >= 4 ? 96 : 0);
            sts64(nbase + SM_A + (uint32_t)(am * ROWB + colb), dotpack(v0), dotpack(v1));
        };
        auto b_async = [&](int chunk, uint32_t base) {
            const int tap = chunk >> 1;
            const int c0  = (chunk & 1) * 128;
#pragma unroll
            for (int q2 = 0; q2 < 8; q2++) {
                const int v2 = t + 512 * q2;
                const int n = v2 >> 4, vw = v2 & 15;
                const size_t gofs = (size_t)n * KTOT + tap * 256 + c0 + vw * 8;
                const uint32_t bo = (uint32_t)(n * ROWB + vw * 16);
                cpasync16(base + SM_B + bo, g_bf + gofs);
            }
            CP_COMMIT();
        };
        auto pass_step = [&](uint32_t base, int s) {
            const uint32_t A = base + SM_A;
            const uint32_t B = base + SM_B;
            uint32_t bf[4][2];
#pragma unroll
            for (int np = 0; np < 2; np++) {
                uint32_t r[4];
                ldm_x4(r, B + (b_row + np * 16) * ROWB + b_colb + s * 32);
                bf[np * 2][0] = r[0]; bf[np * 2][1] = r[1];
                bf[np * 2 + 1][0] = r[2]; bf[np * 2 + 1][1] = r[3];
            }
#pragma unroll
            for (int mi = 0; mi < 4; mi++) {
                uint32_t af[4];
                ldm_x4(af, A + (a_row + mi * 16) * ROWB + a_colb + s * 32);
#pragma unroll
                for (int ni = 0; ni < 4; ni++)
                    mma_fp16(acc[mi][ni], af, bf[ni]);
            }
        };

        // prologue
        b_async(0, sb);
        set_meta(0, sb, true);
        {
            uint32_t u0[4], u1[4];
#pragma unroll
            for (int s = 0; s < 8; s++) {
                a_load4(2 * s, u0); a_load4(2 * s + 1, u1);
                a_finish2(s, u0, u1);
            }
        }
        CP_WAIT0();
        __syncthreads();

        for (int chunk = 0; chunk < NCH2; chunk++) {
            const uint32_t cur = sb + (uint32_t)(chunk & 1) * BUF_BYTES;
            const bool hn = (chunk + 1 < NCH2);
            uint32_t v0[4], v1[4];
            if (hn) {
                const uint32_t nxt = sb + (uint32_t)((chunk + 1) & 1) * BUF_BYTES;
                b_async(chunk + 1, nxt);
                set_meta(chunk + 1, nxt, (((chunk + 1) & 1) == 0));
                a_load4(0, v0); a_load4(1, v1);
            }
#pragma unroll
            for (int s = 0; s < 8; s++) {
                pass_step(cur, s);
                if (hn) {
                    if (s < 7) {
                        a_finish2(s, v0, v1);
                        a_load4(2 * s + 2, v0); a_load4(2 * s + 3, v1);
                    } else {
                        a_finish2(7, v0, v1);
                    }
                }
            }
            if (hn) CP_WAIT0();
            __syncthreads();
        }

        // epilogue
        float* ob = out + (size_t)b * COUT * HW + p0;
        const int mbase = mw * 64 + (lane >> 2);
        const int nbase2 = nw * 32 + (lane & 3) * 2;
#pragma unroll
        for (int mi = 0; mi < 4; mi++) {
#pragma unroll
            for (int ni = 0; ni < 4; ni++) {
                const int m = mbase + mi * 16;
                const int n = nbase2 + ni * 8;
                ob[(size_t)n * HW + m]           = acc[mi][ni][0];
                ob[(size_t)(n + 1) * HW + m]     = acc[mi][ni][1];
                ob[(size_t)n * HW + m + 8]       = acc[mi][ni][2];
                ob[(size_t)(n + 1) * HW + m + 8] = acc[mi][ni][3];
            }
        }
    }
}

// ---------------------------------------------------------------------------
extern "C" void kernel_launch(void* const* d_in, const int* in_sizes, int n_in,
                              void* d_out, int out_size)
{
    (void)in_sizes; (void)n_in; (void)out_size;
    const float* x      = (const float*)d_in[0];
    const float* w_off  = (const float*)d_in[1];
    const float* b_off  = (const float*)d_in[2];
    const float* w_conv = (const float*)d_in[3];
    float* out = (float*)d_out;

    cudaFuncSetAttribute(fused_kernel,
                         cudaFuncAttributeMaxDynamicSharedMemorySize, SMEM_TOTAL);

    prepack_kernel<<<((COUT + 32) * KTOT + 255) / 256, 256>>>(w_conv, w_off);
    prepack_x_kernel<<<BATCH * CPAIR * HW / 256, 256>>>(x);
    fused_kernel<<<128, 512, SMEM_TOTAL>>>(b_off, out);
}